// round 1
// baseline (speedup 1.0000x reference)
#include <cuda_runtime.h>
#include <cuda_bf16.h>
#include <math.h>

#define N_NODES 100000
#define N_EDGES 800000

// ---------------- scratch (device globals; no allocs allowed) ----------------
__device__ float g_h0  [(size_t)N_NODES * 128];
__device__ float g_agg0[(size_t)N_NODES * 128];
__device__ float g_h1  [(size_t)N_NODES * 256];
__device__ float g_agg1[(size_t)N_NODES * 256];
__device__ float g_h2  [(size_t)N_NODES * 128];
__device__ float g_hf  [(size_t)N_NODES * 128];
__device__ float g_c1  [(size_t)N_NODES * 64];
__device__ float g_deg [N_NODES];

// ---------------- generic fused GEMM ----------------
// C[M,N] = relu?( bn?( [A0|A1] @ [W0;W1] + bias ) )
// A0: [M,K0] row-major, A1: [M,K1] row-major (A1 may be null if K1==0)
// W0: [K0,N] row-major, W1: [K1,N] row-major
// bn folded: y = (acc + bias - m) * g/sqrt(v+eps) + b
#define BM 64
#define BN 64
#define BK 16
#define TM 4
#define TN 4

__global__ __launch_bounds__(256) void gemm_fused(
    const float* __restrict__ A0, int K0,
    const float* __restrict__ A1, int K1,
    const float* __restrict__ W0, const float* __restrict__ W1,
    int M, int N,
    const float* __restrict__ bias,
    const float* __restrict__ bng, const float* __restrict__ bnb,
    const float* __restrict__ bnm, const float* __restrict__ bnv,
    int do_relu,
    float* __restrict__ C)
{
    const int K = K0 + K1;
    __shared__ float As[BK][BM];
    __shared__ float Ws[BK][BN];

    const int tid = threadIdx.x;
    const int block_row = blockIdx.y * BM;
    const int block_col = blockIdx.x * BN;

    const int tr = (tid / 16) * TM;   // 0..60
    const int tc = (tid % 16) * TN;   // 0..60

    float acc[TM][TN];
#pragma unroll
    for (int i = 0; i < TM; i++)
#pragma unroll
        for (int j = 0; j < TN; j++) acc[i][j] = 0.f;

    // A loader: each thread loads 4 consecutive k for one row
    const int a_row = tid >> 2;            // 0..63
    const int a_k4  = (tid & 3) * 4;       // 0,4,8,12
    // W loader: each thread loads 4 consecutive n for one k
    const int w_k   = tid >> 4;            // 0..15
    const int w_n4  = (tid & 15) * 4;      // 0..60

    const int gr = block_row + a_row;

    for (int kt = 0; kt < K; kt += BK) {
        // load A tile (transposed into smem)
#pragma unroll
        for (int i = 0; i < 4; i++) {
            const int gk = kt + a_k4 + i;
            float v = 0.f;
            if (gr < M) {
                if (gk < K0) v = A0[(size_t)gr * K0 + gk];
                else         v = A1[(size_t)gr * K1 + (gk - K0)];
            }
            As[a_k4 + i][a_row] = v;
        }
        // load W tile
        {
            const int gk = kt + w_k;
            const float* Wp;
            int kk;
            if (gk < K0) { Wp = W0; kk = gk; }
            else         { Wp = W1; kk = gk - K0; }
#pragma unroll
            for (int i = 0; i < 4; i++) {
                const int gn = block_col + w_n4 + i;
                Ws[w_k][w_n4 + i] = (gn < N) ? Wp[(size_t)kk * N + gn] : 0.f;
            }
        }
        __syncthreads();

#pragma unroll
        for (int kk = 0; kk < BK; kk++) {
            float a[TM], w[TN];
#pragma unroll
            for (int i = 0; i < TM; i++) a[i] = As[kk][tr + i];
#pragma unroll
            for (int j = 0; j < TN; j++) w[j] = Ws[kk][tc + j];
#pragma unroll
            for (int i = 0; i < TM; i++)
#pragma unroll
                for (int j = 0; j < TN; j++)
                    acc[i][j] += a[i] * w[j];
        }
        __syncthreads();
    }

    // epilogue
#pragma unroll
    for (int j = 0; j < TN; j++) {
        const int gn = block_col + tc + j;
        if (gn >= N) continue;
        float sc = 1.f, sh = 0.f;
        if (bias) sh = bias[gn];
        if (bng) {
            const float g = bng[gn], bb = bnb[gn], m = bnm[gn], vv = bnv[gn];
            const float s = g * rsqrtf(vv + 1e-5f);
            sh = (sh - m) * s + bb;
            sc = s;
        }
#pragma unroll
        for (int i = 0; i < TM; i++) {
            const int gm = block_row + tr + i;
            if (gm >= M) continue;
            float v = acc[i][j] * sc + sh;
            if (do_relu) v = fmaxf(v, 0.f);
            C[(size_t)gm * N + gn] = v;
        }
    }
}

// ---------------- graph aggregation ----------------
__global__ void compute_deg(const int* __restrict__ dst, float* __restrict__ deg, int E)
{
    int e = blockIdx.x * blockDim.x + threadIdx.x;
    if (e < E) atomicAdd(&deg[dst[e]], 1.0f);
}

// one warp per edge; D is a multiple of 128
__global__ void scatter_add(const float* __restrict__ h, const int* __restrict__ src,
                            const int* __restrict__ dst, float* __restrict__ sum,
                            int E, int D)
{
    const int lane   = threadIdx.x & 31;
    const int warp   = (blockIdx.x * blockDim.x + threadIdx.x) >> 5;
    const int nwarps = (gridDim.x * blockDim.x) >> 5;
    const int D4 = D >> 2;
    for (int e = warp; e < E; e += nwarps) {
        const int s = src[e];
        const int d = dst[e];
        const float4* hs = (const float4*)(h + (size_t)s * D);
        float* ds = sum + (size_t)d * D;
        for (int c = lane; c < D4; c += 32) {
            float4 v = hs[c];
            atomicAdd(ds + c * 4 + 0, v.x);
            atomicAdd(ds + c * 4 + 1, v.y);
            atomicAdd(ds + c * 4 + 2, v.z);
            atomicAdd(ds + c * 4 + 3, v.w);
        }
    }
}

__global__ void scale_by_deg(float* __restrict__ sum, const float* __restrict__ deg,
                             int Nn, int D)
{
    size_t i = (size_t)blockIdx.x * blockDim.x + threadIdx.x;
    size_t total = (size_t)Nn * D;
    if (i < total) {
        float d = deg[i / D];
        sum[i] *= 1.f / fmaxf(d, 1.f);
    }
}

// ---------------- launch ----------------
static inline void launch_gemm(const float* A0, int K0, const float* A1, int K1,
                               const float* W0, const float* W1,
                               int M, int N,
                               const float* bias,
                               const float* bng, const float* bnb,
                               const float* bnm, const float* bnv,
                               int do_relu, float* C)
{
    dim3 grid((N + BN - 1) / BN, (M + BM - 1) / BM);
    gemm_fused<<<grid, 256>>>(A0, K0, A1, K1, W0, W1, M, N,
                              bias, bng, bnb, bnm, bnv, do_relu, C);
}

extern "C" void kernel_launch(void* const* d_in, const int* in_sizes, int n_in,
                              void* d_out, int out_size)
{
    const float* structural = (const float*)d_in[0];   // [N,128]
    const float* multimodal = (const float*)d_in[1];   // [N,384]
    const int*   src        = (const int*)  d_in[2];   // [E]
    const int*   dst        = (const int*)  d_in[3];   // [E]
    const float* enc_w      = (const float*)d_in[4];   // [512,128]
    const float* enc_b      = (const float*)d_in[5];
    const float* sage0_ws   = (const float*)d_in[6];   // [128,256]
    const float* sage0_wn   = (const float*)d_in[7];
    const float* sage0_b    = (const float*)d_in[8];
    const float* bn0_g      = (const float*)d_in[9];
    const float* bn0_b      = (const float*)d_in[10];
    const float* bn0_m      = (const float*)d_in[11];
    const float* bn0_v      = (const float*)d_in[12];
    const float* sage1_ws   = (const float*)d_in[13];  // [256,128]
    const float* sage1_wn   = (const float*)d_in[14];
    const float* sage1_b    = (const float*)d_in[15];
    const float* bn1_g      = (const float*)d_in[16];
    const float* bn1_b      = (const float*)d_in[17];
    const float* bn1_m      = (const float*)d_in[18];
    const float* bn1_v      = (const float*)d_in[19];
    const float* rel_w      = (const float*)d_in[20];  // [256,128]
    const float* rel_b      = (const float*)d_in[21];
    const float* cls_w1     = (const float*)d_in[22];  // [128,64]
    const float* cls_b1     = (const float*)d_in[23];
    const float* cls_w2     = (const float*)d_in[24];  // [64,32]
    const float* cls_b2     = (const float*)d_in[25];
    float* out = (float*)d_out;                        // [N,32]

    void *p_h0, *p_agg0, *p_h1, *p_agg1, *p_h2, *p_hf, *p_c1, *p_deg;
    cudaGetSymbolAddress(&p_h0,   g_h0);
    cudaGetSymbolAddress(&p_agg0, g_agg0);
    cudaGetSymbolAddress(&p_h1,   g_h1);
    cudaGetSymbolAddress(&p_agg1, g_agg1);
    cudaGetSymbolAddress(&p_h2,   g_h2);
    cudaGetSymbolAddress(&p_hf,   g_hf);
    cudaGetSymbolAddress(&p_c1,   g_c1);
    cudaGetSymbolAddress(&p_deg,  g_deg);
    float* h0   = (float*)p_h0;
    float* agg0 = (float*)p_agg0;
    float* h1   = (float*)p_h1;
    float* agg1 = (float*)p_agg1;
    float* h2   = (float*)p_h2;
    float* hf   = (float*)p_hf;
    float* c1   = (float*)p_c1;
    float* deg  = (float*)p_deg;

    const int M = N_NODES, E = N_EDGES;

    // zero accumulators (graph-capturable async memsets)
    cudaMemsetAsync(deg,  0, (size_t)N_NODES * sizeof(float), 0);
    cudaMemsetAsync(agg0, 0, (size_t)N_NODES * 128 * sizeof(float), 0);
    cudaMemsetAsync(agg1, 0, (size_t)N_NODES * 256 * sizeof(float), 0);

    // degrees (same graph for both layers)
    compute_deg<<<(E + 255) / 256, 256>>>(dst, deg, E);

    // h0 = relu([structural|multimodal] @ enc_w + enc_b)   [N,128]
    launch_gemm(structural, 128, multimodal, 384,
                enc_w, enc_w + (size_t)128 * 128,
                M, 128, enc_b, nullptr, nullptr, nullptr, nullptr, 1, h0);

    // agg0 = mean_{src->dst} h0
    scatter_add<<<2048, 256>>>(h0, src, dst, agg0, E, 128);
    {
        size_t total = (size_t)M * 128;
        scale_by_deg<<<(int)((total + 255) / 256), 256>>>(agg0, deg, M, 128);
    }

    // h1 = relu(bn0(h0 @ ws0 + agg0 @ wn0 + b0))   [N,256]
    launch_gemm(h0, 128, agg0, 128, sage0_ws, sage0_wn,
                M, 256, sage0_b, bn0_g, bn0_b, bn0_m, bn0_v, 1, h1);

    // agg1 = mean_{src->dst} h1
    scatter_add<<<2048, 256>>>(h1, src, dst, agg1, E, 256);
    {
        size_t total = (size_t)M * 256;
        scale_by_deg<<<(int)((total + 255) / 256), 256>>>(agg1, deg, M, 256);
    }

    // h2 = relu(bn1(h1 @ ws1 + agg1 @ wn1 + b1))   [N,128]
    launch_gemm(h1, 256, agg1, 256, sage1_ws, sage1_wn,
                M, 128, sage1_b, bn1_g, bn1_b, bn1_m, bn1_v, 1, h2);

    // hf = relu([h0|h2] @ rel_w + rel_b)   [N,128]
    launch_gemm(h0, 128, h2, 128, rel_w, rel_w + (size_t)128 * 128,
                M, 128, rel_b, nullptr, nullptr, nullptr, nullptr, 1, hf);

    // c1 = relu(hf @ cls_w1 + cls_b1)   [N,64]
    launch_gemm(hf, 128, nullptr, 0, cls_w1, cls_w1,
                M, 64, cls_b1, nullptr, nullptr, nullptr, nullptr, 1, c1);

    // out = c1 @ cls_w2 + cls_b2   [N,32]
    launch_gemm(c1, 64, nullptr, 0, cls_w2, cls_w2,
                M, 32, cls_b2, nullptr, nullptr, nullptr, nullptr, 0, out);
}

// round 3
// speedup vs baseline: 1.9474x; 1.9474x over previous
#include <cuda_runtime.h>
#include <math.h>
#include <stdint.h>

#define N_NODES 100000
#define N_EDGES 800000

// ---------------- scratch (device globals; no allocs allowed) ----------------
__device__ float g_h0  [(size_t)N_NODES * 128];
__device__ float g_agg0[(size_t)N_NODES * 128];
__device__ float g_h1  [(size_t)N_NODES * 256];
__device__ float g_agg1[(size_t)N_NODES * 256];
__device__ float g_h2  [(size_t)N_NODES * 128];
__device__ float g_hf  [(size_t)N_NODES * 128];
__device__ float g_c1  [(size_t)N_NODES * 64];
__device__ float g_deg [N_NODES];

// ---------------- 3xTF32 tensor-core GEMM ----------------
// C[M,N] = relu?( bn?( [A0|A1] @ [W0;W1] + bias ) )
// Block tile 128x64, K-tile 32, 256 threads (8 warps, 4x2 of 32x32 warp tiles),
// cp.async double-buffered smem, mma.sync.m16n8k8.tf32 with hi/lo split
// (acc += ah*bh + al*bh + ah*bl) for ~fp32 precision.
#define BM 128
#define BN 64
#define BK 32
#define AS_STRIDE 36
#define BS_STRIDE 68
#define AS_FLOATS (BM * AS_STRIDE)
#define BS_FLOATS (BK * BS_STRIDE)
#define GEMM_SMEM_BYTES (2 * (AS_FLOATS + BS_FLOATS) * 4)  // 54272

__device__ __forceinline__ void cp16(uint32_t dst, const void* src, bool pred) {
    asm volatile("cp.async.cg.shared.global [%0], [%1], 16, %2;"
                 :: "r"(dst), "l"(src), "r"(pred ? 16 : 0));
}

__device__ __forceinline__ void split_tf32(float x, uint32_t& hi, uint32_t& lo) {
    uint32_t h;
    asm("cvt.rna.tf32.f32 %0, %1;" : "=r"(h) : "f"(x));
    float r = x - __uint_as_float(h);
    uint32_t l;
    asm("cvt.rna.tf32.f32 %0, %1;" : "=r"(l) : "f"(r));
    hi = h; lo = l;
}

#define MMA_TF32(acc, a, b)                                                     \
    asm volatile(                                                               \
        "mma.sync.aligned.m16n8k8.row.col.f32.tf32.tf32.f32 "                   \
        "{%0,%1,%2,%3},{%4,%5,%6,%7},{%8,%9},{%0,%1,%2,%3};"                    \
        : "+f"((acc)[0]), "+f"((acc)[1]), "+f"((acc)[2]), "+f"((acc)[3])        \
        : "r"((a)[0]), "r"((a)[1]), "r"((a)[2]), "r"((a)[3]),                   \
          "r"((b)[0]), "r"((b)[1]))

__global__ __launch_bounds__(256) void gemm_tf32(
    const float* __restrict__ A0, int K0,
    const float* __restrict__ A1, int K1,
    const float* __restrict__ W0, const float* __restrict__ W1,
    int M, int N,
    const float* __restrict__ bias,
    const float* __restrict__ bng, const float* __restrict__ bnb,
    const float* __restrict__ bnm, const float* __restrict__ bnv,
    int do_relu,
    float* __restrict__ C)
{
    extern __shared__ float smem[];
    float* AsBuf[2] = { smem, smem + AS_FLOATS };
    float* BsBuf[2] = { smem + 2 * AS_FLOATS, smem + 2 * AS_FLOATS + BS_FLOATS };

    const int tid  = threadIdx.x;
    const int lane = tid & 31;
    const int wid  = tid >> 5;
    const int wm   = (wid & 3) * 32;
    const int wn   = (wid >> 2) * 32;
    const int brow = blockIdx.y * BM;
    const int bcol = blockIdx.x * BN;
    const int K = K0 + K1;
    const int T = K / BK;

    const int a_row = tid >> 1;
    const int a_kq  = (tid & 1) * 16;
    const int a_gr  = brow + a_row;
    const bool a_ok = (a_gr < M);

    const int b_k = tid >> 3;
    const int b_n = (tid & 7) * 4;

    float acc[2][4][4];
#pragma unroll
    for (int mt = 0; mt < 2; mt++)
#pragma unroll
        for (int nt = 0; nt < 4; nt++)
#pragma unroll
            for (int i = 0; i < 4; i++) acc[mt][nt][i] = 0.f;

#define LOAD_TILE(t, s) do {                                                      \
        const int kt_ = (t) * BK;                                                 \
        float* as_ = AsBuf[s];                                                    \
        float* bs_ = BsBuf[s];                                                    \
        { int gk0 = kt_ + a_kq;                                                   \
          const float* sp;                                                        \
          if (gk0 < K0) sp = A0 + (size_t)a_gr * K0 + gk0;                        \
          else          sp = A1 + (size_t)a_gr * K1 + (gk0 - K0);                 \
          uint32_t d = (uint32_t)__cvta_generic_to_shared(                        \
                           as_ + a_row * AS_STRIDE + a_kq);                       \
          cp16(d,      sp,      a_ok);                                            \
          cp16(d + 16, sp + 4,  a_ok);                                            \
          cp16(d + 32, sp + 8,  a_ok);                                            \
          cp16(d + 48, sp + 12, a_ok);                                            \
        }                                                                         \
        { int gk = kt_ + b_k;                                                     \
          const float* wp; int kk2;                                               \
          if (gk < K0) { wp = W0; kk2 = gk; }                                     \
          else         { wp = W1; kk2 = gk - K0; }                                \
          uint32_t d = (uint32_t)__cvta_generic_to_shared(                        \
                           bs_ + b_k * BS_STRIDE + b_n);                          \
          int n0 = bcol + b_n;                                                    \
          cp16(d,       wp + (size_t)kk2 * N + n0,      n0 < N);                  \
          cp16(d + 128, wp + (size_t)kk2 * N + n0 + 32, (n0 + 32) < N);           \
        }                                                                         \
        asm volatile("cp.async.commit_group;");                                   \
    } while (0)

    LOAD_TILE(0, 0);

    for (int t = 0; t < T; ++t) {
        const int s = t & 1;
        if (t + 1 < T) {
            LOAD_TILE(t + 1, s ^ 1);
            asm volatile("cp.async.wait_group 1;");
        } else {
            asm volatile("cp.async.wait_group 0;");
        }
        __syncthreads();

        const float* as_ = AsBuf[s];
        const float* bs_ = BsBuf[s];
#pragma unroll
        for (int k8 = 0; k8 < 4; k8++) {
            const int kk = k8 * 8 + (lane & 3);
            uint32_t ah[2][4], al[2][4], bh[4][2], bl[4][2];
            const int r0 = wm + (lane >> 2);
#pragma unroll
            for (int mt = 0; mt < 2; mt++) {
                const float* p = as_ + (r0 + 16 * mt) * AS_STRIDE + kk;
                split_tf32(p[0],                  ah[mt][0], al[mt][0]);
                split_tf32(p[8 * AS_STRIDE],      ah[mt][1], al[mt][1]);
                split_tf32(p[4],                  ah[mt][2], al[mt][2]);
                split_tf32(p[8 * AS_STRIDE + 4],  ah[mt][3], al[mt][3]);
            }
#pragma unroll
            for (int nt = 0; nt < 4; nt++) {
                const int col = wn + 8 * nt + (lane >> 2);
                split_tf32(bs_[kk * BS_STRIDE + col],       bh[nt][0], bl[nt][0]);
                split_tf32(bs_[(kk + 4) * BS_STRIDE + col], bh[nt][1], bl[nt][1]);
            }
#pragma unroll
            for (int mt = 0; mt < 2; mt++)
#pragma unroll
                for (int nt = 0; nt < 4; nt++) {
                    MMA_TF32(acc[mt][nt], al[mt], bh[nt]);
                    MMA_TF32(acc[mt][nt], ah[mt], bl[nt]);
                    MMA_TF32(acc[mt][nt], ah[mt], bh[nt]);
                }
        }
        __syncthreads();
    }

    // ---------------- epilogue: bias / bn / relu, float2 stores ----------------
#pragma unroll
    for (int nt = 0; nt < 4; nt++) {
        const int col = bcol + wn + 8 * nt + 2 * (lane & 3);
        if (col >= N) continue;
        float sc0 = 1.f, sh0 = 0.f, sc1 = 1.f, sh1 = 0.f;
        if (bias) { sh0 = bias[col]; sh1 = bias[col + 1]; }
        if (bng) {
            float s0 = bng[col]     * rsqrtf(bnv[col]     + 1e-5f);
            float s1 = bng[col + 1] * rsqrtf(bnv[col + 1] + 1e-5f);
            sh0 = (sh0 - bnm[col])     * s0 + bnb[col];
            sh1 = (sh1 - bnm[col + 1]) * s1 + bnb[col + 1];
            sc0 = s0; sc1 = s1;
        }
#pragma unroll
        for (int mt = 0; mt < 2; mt++) {
            const int row = brow + wm + 16 * mt + (lane >> 2);
            const float* c = acc[mt][nt];
            if (row < M) {
                float v0 = c[0] * sc0 + sh0;
                float v1 = c[1] * sc1 + sh1;
                if (do_relu) { v0 = fmaxf(v0, 0.f); v1 = fmaxf(v1, 0.f); }
                *(float2*)(C + (size_t)row * N + col) = make_float2(v0, v1);
            }
            if (row + 8 < M) {
                float v0 = c[2] * sc0 + sh0;
                float v1 = c[3] * sc1 + sh1;
                if (do_relu) { v0 = fmaxf(v0, 0.f); v1 = fmaxf(v1, 0.f); }
                *(float2*)(C + (size_t)(row + 8) * N + col) = make_float2(v0, v1);
            }
        }
    }
}

// ---------------- graph aggregation ----------------
__global__ void compute_deg(const int* __restrict__ dst, float* __restrict__ deg, int E)
{
    int e = blockIdx.x * blockDim.x + threadIdx.x;
    if (e < E) atomicAdd(&deg[dst[e]], 1.0f);
}

__global__ void finalize_deg(float* __restrict__ deg, int n)
{
    int i = blockIdx.x * blockDim.x + threadIdx.x;
    if (i < n) deg[i] = 1.f / fmaxf(deg[i], 1.f);
}

// one warp per edge; mean-scaling folded in; vector (v4) float reductions
__global__ void scatter_mean(const float* __restrict__ h, const int* __restrict__ src,
                             const int* __restrict__ dst, const float* __restrict__ invdeg,
                             float* __restrict__ sum, int E, int D4)
{
    const int warp = (blockIdx.x * blockDim.x + threadIdx.x) >> 5;
    const int lane = threadIdx.x & 31;
    if (warp >= E) return;
    const int s = src[warp];
    const int d = dst[warp];
    const float inv = invdeg[d];
    const float4* hs = (const float4*)h + (size_t)s * D4;
    float* ds = sum + (size_t)d * (D4 * 4);
#pragma unroll 2
    for (int c = lane; c < D4; c += 32) {
        float4 v = hs[c];
        v.x *= inv; v.y *= inv; v.z *= inv; v.w *= inv;
        asm volatile("red.global.add.v4.f32 [%0], {%1,%2,%3,%4};"
                     :: "l"(ds + (size_t)c * 4),
                        "f"(v.x), "f"(v.y), "f"(v.z), "f"(v.w)
                     : "memory");
    }
}

// ---------------- launch helpers ----------------
static inline void launch_gemm(const float* A0, int K0, const float* A1, int K1,
                               const float* W0, const float* W1,
                               int M, int N,
                               const float* bias,
                               const float* bng, const float* bnb,
                               const float* bnm, const float* bnv,
                               int do_relu, float* C)
{
    dim3 grid((N + BN - 1) / BN, (M + BM - 1) / BM);
    gemm_tf32<<<grid, 256, GEMM_SMEM_BYTES>>>(A0, K0, A1, K1, W0, W1, M, N,
                                              bias, bng, bnb, bnm, bnv, do_relu, C);
}

extern "C" void kernel_launch(void* const* d_in, const int* in_sizes, int n_in,
                              void* d_out, int out_size)
{
    const float* structural = (const float*)d_in[0];   // [N,128]
    const float* multimodal = (const float*)d_in[1];   // [N,384]
    const int*   src        = (const int*)  d_in[2];   // [E]
    const int*   dst        = (const int*)  d_in[3];   // [E]
    const float* enc_w      = (const float*)d_in[4];   // [512,128]
    const float* enc_b      = (const float*)d_in[5];
    const float* sage0_ws   = (const float*)d_in[6];   // [128,256]
    const float* sage0_wn   = (const float*)d_in[7];
    const float* sage0_b    = (const float*)d_in[8];
    const float* bn0_g      = (const float*)d_in[9];
    const float* bn0_b      = (const float*)d_in[10];
    const float* bn0_m      = (const float*)d_in[11];
    const float* bn0_v      = (const float*)d_in[12];
    const float* sage1_ws   = (const float*)d_in[13];  // [256,128]
    const float* sage1_wn   = (const float*)d_in[14];
    const float* sage1_b    = (const float*)d_in[15];
    const float* bn1_g      = (const float*)d_in[16];
    const float* bn1_b      = (const float*)d_in[17];
    const float* bn1_m      = (const float*)d_in[18];
    const float* bn1_v      = (const float*)d_in[19];
    const float* rel_w      = (const float*)d_in[20];  // [256,128]
    const float* rel_b      = (const float*)d_in[21];
    const float* cls_w1     = (const float*)d_in[22];  // [128,64]
    const float* cls_b1     = (const float*)d_in[23];
    const float* cls_w2     = (const float*)d_in[24];  // [64,32]
    const float* cls_b2     = (const float*)d_in[25];
    float* out = (float*)d_out;                        // [N,32]

    void *p_h0, *p_agg0, *p_h1, *p_agg1, *p_h2, *p_hf, *p_c1, *p_deg;
    cudaGetSymbolAddress(&p_h0,   g_h0);
    cudaGetSymbolAddress(&p_agg0, g_agg0);
    cudaGetSymbolAddress(&p_h1,   g_h1);
    cudaGetSymbolAddress(&p_agg1, g_agg1);
    cudaGetSymbolAddress(&p_h2,   g_h2);
    cudaGetSymbolAddress(&p_hf,   g_hf);
    cudaGetSymbolAddress(&p_c1,   g_c1);
    cudaGetSymbolAddress(&p_deg,  g_deg);
    float* h0   = (float*)p_h0;
    float* agg0 = (float*)p_agg0;
    float* h1   = (float*)p_h1;
    float* agg1 = (float*)p_agg1;
    float* h2   = (float*)p_h2;
    float* hf   = (float*)p_hf;
    float* c1   = (float*)p_c1;
    float* deg  = (float*)p_deg;

    cudaFuncSetAttribute(gemm_tf32, cudaFuncAttributeMaxDynamicSharedMemorySize,
                         GEMM_SMEM_BYTES);

    const int M = N_NODES, E = N_EDGES;

    // zero accumulators (graph-capturable)
    cudaMemsetAsync(deg,  0, (size_t)N_NODES * sizeof(float), 0);
    cudaMemsetAsync(agg0, 0, (size_t)N_NODES * 128 * sizeof(float), 0);
    cudaMemsetAsync(agg1, 0, (size_t)N_NODES * 256 * sizeof(float), 0);

    // degree -> inverse degree (same graph both layers)
    compute_deg<<<(E + 255) / 256, 256>>>(dst, deg, E);
    finalize_deg<<<(M + 255) / 256, 256>>>(deg, M);

    // h0 = relu([structural|multimodal] @ enc_w + enc_b)   [N,128]
    launch_gemm(structural, 128, multimodal, 384,
                enc_w, enc_w + (size_t)128 * 128,
                M, 128, enc_b, nullptr, nullptr, nullptr, nullptr, 1, h0);

    // agg0 = mean_{src->dst} h0   (scaling fused into scatter)
    scatter_mean<<<(E * 32 + 255) / 256, 256>>>(h0, src, dst, deg, agg0, E, 128 / 4);

    // h1 = relu(bn0(h0 @ ws0 + agg0 @ wn0 + b0))   [N,256]
    launch_gemm(h0, 128, agg0, 128, sage0_ws, sage0_wn,
                M, 256, sage0_b, bn0_g, bn0_b, bn0_m, bn0_v, 1, h1);

    // agg1 = mean_{src->dst} h1
    scatter_mean<<<(E * 32 + 255) / 256, 256>>>(h1, src, dst, deg, agg1, E, 256 / 4);

    // h2 = relu(bn1(h1 @ ws1 + agg1 @ wn1 + b1))   [N,128]
    launch_gemm(h1, 256, agg1, 256, sage1_ws, sage1_wn,
                M, 128, sage1_b, bn1_g, bn1_b, bn1_m, bn1_v, 1, h2);

    // hf = relu([h0|h2] @ rel_w + rel_b)   [N,128]
    launch_gemm(h0, 128, h2, 128, rel_w, rel_w + (size_t)128 * 128,
                M, 128, rel_b, nullptr, nullptr, nullptr, nullptr, 1, hf);

    // c1 = relu(hf @ cls_w1 + cls_b1)   [N,64]
    launch_gemm(hf, 128, nullptr, 0, cls_w1, cls_w1,
                M, 64, cls_b1, nullptr, nullptr, nullptr, nullptr, 1, c1);

    // out = c1 @ cls_w2 + cls_b2   [N,32]
    launch_gemm(c1, 64, nullptr, 0, cls_w2, cls_w2,
                M, 32, cls_b2, nullptr, nullptr, nullptr, nullptr, 0, out);
}

// round 4
// speedup vs baseline: 2.7348x; 1.4043x over previous
#include <cuda_runtime.h>
#include <cuda_bf16.h>
#include <math.h>
#include <stdint.h>

#define N_NODES 100000
#define N_EDGES 800000

typedef __nv_bfloat16  bf16;
typedef __nv_bfloat162 bf162;

// ---------------- scratch (device globals; no allocs allowed) ----------------
// bf16 hi/lo planes for all GEMM operands
__device__ bf16 g_xsh[(size_t)N_NODES * 128], g_xsl[(size_t)N_NODES * 128];
__device__ bf16 g_xmh[(size_t)N_NODES * 384], g_xml[(size_t)N_NODES * 384];
__device__ bf16 g_h0h[(size_t)N_NODES * 128], g_h0l[(size_t)N_NODES * 128];
__device__ bf16 g_a0h[(size_t)N_NODES * 128], g_a0l[(size_t)N_NODES * 128];
__device__ bf16 g_h1h[(size_t)N_NODES * 256], g_h1l[(size_t)N_NODES * 256];
__device__ bf16 g_a1h[(size_t)N_NODES * 256], g_a1l[(size_t)N_NODES * 256];
__device__ bf16 g_h2h[(size_t)N_NODES * 128], g_h2l[(size_t)N_NODES * 128];
__device__ bf16 g_hfh[(size_t)N_NODES * 128], g_hfl[(size_t)N_NODES * 128];
__device__ bf16 g_c1h[(size_t)N_NODES * 64],  g_c1l[(size_t)N_NODES * 64];
__device__ float g_agg0[(size_t)N_NODES * 128];
__device__ float g_agg1[(size_t)N_NODES * 256];
__device__ float g_deg [N_NODES];
__device__ bf16 g_wh[262144], g_wl[262144];

// weight plane offsets (elements)
#define WOFF_ENC 0
#define WOFF_S0S 65536
#define WOFF_S0N 98304
#define WOFF_S1S 131072
#define WOFF_S1N 163840
#define WOFF_REL 196608
#define WOFF_C1  229376
#define WOFF_C2  237568

// ---------------- bf16x3 tensor-core GEMM ----------------
// C[M,N] = relu?( bn?( [A0|A1] @ [W0;W1] + bias ) )
// Operands given as bf16 hi/lo planes: X = Xh + Xl exactly to ~2^-18.
// acc += Al*Bh + Ah*Bl + Ah*Bh  (dropped Al*Bl ~ 2^-18 relative)
// Block 128x64, K-tile 32, 8 warps (4x2 of 32x32), cp.async double buffer,
// ldmatrix fragment loads, mma.sync.m16n8k16.bf16.
#define BM 128
#define BN 64
#define BK 32
#define A_STRIDE 40            // bf16 units (80B rows: conflict-free ldmatrix)
#define B_STRIDE 72            // bf16 units (144B rows: conflict-free ldmatrix)
#define A_PLANE (BM * A_STRIDE)          // 5120
#define B_PLANE (BK * B_STRIDE)          // 2304
#define STAGE_ELEMS (2 * A_PLANE + 2 * B_PLANE)   // 14848
#define GEMM_SMEM_BYTES (2 * STAGE_ELEMS * 2)     // 59392

__device__ __forceinline__ void cp16(uint32_t dst, const void* src, bool pred) {
    asm volatile("cp.async.cg.shared.global [%0], [%1], 16, %2;"
                 :: "r"(dst), "l"(src), "r"(pred ? 16 : 0));
}

#define LDMX4(r, addr)                                                          \
    asm volatile("ldmatrix.sync.aligned.m8n8.x4.shared.b16 {%0,%1,%2,%3},[%4];" \
                 : "=r"((r)[0]), "=r"((r)[1]), "=r"((r)[2]), "=r"((r)[3])       \
                 : "r"(addr))

#define LDMX4T(r, addr)                                                         \
    asm volatile("ldmatrix.sync.aligned.m8n8.x4.trans.shared.b16 "              \
                 "{%0,%1,%2,%3},[%4];"                                          \
                 : "=r"((r)[0]), "=r"((r)[1]), "=r"((r)[2]), "=r"((r)[3])       \
                 : "r"(addr))

#define MMA_BF16(acc, a, b0, b1)                                                \
    asm volatile(                                                               \
        "mma.sync.aligned.m16n8k16.row.col.f32.bf16.bf16.f32 "                  \
        "{%0,%1,%2,%3},{%4,%5,%6,%7},{%8,%9},{%0,%1,%2,%3};"                    \
        : "+f"((acc)[0]), "+f"((acc)[1]), "+f"((acc)[2]), "+f"((acc)[3])        \
        : "r"((a)[0]), "r"((a)[1]), "r"((a)[2]), "r"((a)[3]),                   \
          "r"(b0), "r"(b1))

__global__ __launch_bounds__(256) void gemm_bf16x3(
    const bf16* __restrict__ A0h, const bf16* __restrict__ A0l, int K0,
    const bf16* __restrict__ A1h, const bf16* __restrict__ A1l, int K1,
    const bf16* __restrict__ W0h, const bf16* __restrict__ W0l,
    const bf16* __restrict__ W1h, const bf16* __restrict__ W1l,
    int M, int N,
    const float* __restrict__ bias,
    const float* __restrict__ bng, const float* __restrict__ bnb,
    const float* __restrict__ bnm, const float* __restrict__ bnv,
    int do_relu,
    float* __restrict__ Cf, bf16* __restrict__ Ch, bf16* __restrict__ Cl)
{
    extern __shared__ bf16 smem[];
    const uint32_t smem_u32 = (uint32_t)__cvta_generic_to_shared(smem);

    const int tid  = threadIdx.x;
    const int lane = tid & 31;
    const int wid  = tid >> 5;
    const int wm   = (wid & 3) * 32;
    const int wn   = (wid >> 2) * 32;
    const int brow = blockIdx.y * BM;
    const int bcol = blockIdx.x * BN;
    const int K = K0 + K1;
    const int T = K / BK;

    // A loader: thread -> (row 0..127, k-half 0/16)
    const int a_row = tid >> 1;
    const int a_k   = (tid & 1) * 16;
    const int a_gr  = brow + a_row;
    const bool a_ok = (a_gr < M);
    // B loader: thread -> (k row 0..31, 8-col group)
    const int b_k = tid >> 3;
    const int b_n = (tid & 7) * 8;

    // ldmatrix per-thread offsets (bf16 units within plane)
    const int a_lm = (wm + (lane & 15)) * A_STRIDE + (lane >> 4) * 8;
    const int b_lm = ((lane & 7) + ((lane >> 3) & 1) * 8) * B_STRIDE
                     + wn + (lane >> 4) * 8;

    float acc[2][4][4];
#pragma unroll
    for (int mt = 0; mt < 2; mt++)
#pragma unroll
        for (int nt = 0; nt < 4; nt++)
#pragma unroll
            for (int i = 0; i < 4; i++) acc[mt][nt][i] = 0.f;

#define LOAD_TILE(t, st) do {                                                     \
        const int kt_ = (t) * BK;                                                 \
        { int gk0 = kt_ + a_k;                                                    \
          const bf16 *sph, *spl;                                                  \
          if (gk0 < K0) { sph = A0h + (size_t)a_gr * K0 + gk0;                    \
                          spl = A0l + (size_t)a_gr * K0 + gk0; }                  \
          else          { sph = A1h + (size_t)a_gr * K1 + (gk0 - K0);             \
                          spl = A1l + (size_t)a_gr * K1 + (gk0 - K0); }           \
          uint32_t dh = smem_u32 +                                                \
              ((st) * STAGE_ELEMS + a_row * A_STRIDE + a_k) * 2;                  \
          cp16(dh,      sph,     a_ok);                                           \
          cp16(dh + 16, sph + 8, a_ok);                                           \
          uint32_t dl = dh + A_PLANE * 2;                                         \
          cp16(dl,      spl,     a_ok);                                           \
          cp16(dl + 16, spl + 8, a_ok);                                           \
        }                                                                         \
        { int gk = kt_ + b_k;                                                     \
          const bf16 *wph, *wpl; int kk2;                                         \
          if (gk < K0) { wph = W0h; wpl = W0l; kk2 = gk; }                        \
          else         { wph = W1h; wpl = W1l; kk2 = gk - K0; }                   \
          int n0 = bcol + b_n;                                                    \
          bool ok = (n0 < N);                                                     \
          uint32_t dbh = smem_u32 +                                               \
              ((st) * STAGE_ELEMS + 2 * A_PLANE + b_k * B_STRIDE + b_n) * 2;      \
          cp16(dbh,               wph + (size_t)kk2 * N + n0, ok);                \
          cp16(dbh + B_PLANE * 2, wpl + (size_t)kk2 * N + n0, ok);                \
        }                                                                         \
        asm volatile("cp.async.commit_group;");                                   \
    } while (0)

    LOAD_TILE(0, 0);

    for (int t = 0; t < T; ++t) {
        const int st = t & 1;
        if (t + 1 < T) {
            LOAD_TILE(t + 1, st ^ 1);
            asm volatile("cp.async.wait_group 1;");
        } else {
            asm volatile("cp.async.wait_group 0;");
        }
        __syncthreads();

        const uint32_t base = smem_u32 + st * STAGE_ELEMS * 2;
#pragma unroll
        for (int k16 = 0; k16 < 2; k16++) {
            uint32_t ah[2][4], al[2][4], bh[2][4], bl[2][4];
#pragma unroll
            for (int mt = 0; mt < 2; mt++) {
                uint32_t ad = base + (a_lm + mt * 16 * A_STRIDE + k16 * 16) * 2;
                LDMX4(ah[mt], ad);
                LDMX4(al[mt], ad + A_PLANE * 2);
            }
#pragma unroll
            for (int p = 0; p < 2; p++) {
                uint32_t bd = base + (2 * A_PLANE + b_lm + p * 16
                                      + k16 * 16 * B_STRIDE) * 2;
                LDMX4T(bh[p], bd);
                LDMX4T(bl[p], bd + B_PLANE * 2);
            }
#pragma unroll
            for (int mt = 0; mt < 2; mt++)
#pragma unroll
                for (int nt = 0; nt < 4; nt++) {
                    const int p = nt >> 1, q = (nt & 1) * 2;
                    MMA_BF16(acc[mt][nt], al[mt], bh[p][q], bh[p][q + 1]);
                    MMA_BF16(acc[mt][nt], ah[mt], bl[p][q], bl[p][q + 1]);
                    MMA_BF16(acc[mt][nt], ah[mt], bh[p][q], bh[p][q + 1]);
                }
        }
        __syncthreads();
    }

    // ---------------- epilogue ----------------
#pragma unroll
    for (int nt = 0; nt < 4; nt++) {
        const int col = bcol + wn + 8 * nt + 2 * (lane & 3);
        if (col >= N) continue;
        float sc0 = 1.f, sh0 = 0.f, sc1 = 1.f, sh1 = 0.f;
        if (bias) { sh0 = bias[col]; sh1 = bias[col + 1]; }
        if (bng) {
            float s0 = bng[col]     * rsqrtf(bnv[col]     + 1e-5f);
            float s1 = bng[col + 1] * rsqrtf(bnv[col + 1] + 1e-5f);
            sh0 = (sh0 - bnm[col])     * s0 + bnb[col];
            sh1 = (sh1 - bnm[col + 1]) * s1 + bnb[col + 1];
            sc0 = s0; sc1 = s1;
        }
#pragma unroll
        for (int mt = 0; mt < 2; mt++) {
#pragma unroll
            for (int half = 0; half < 2; half++) {
                const int row = brow + wm + 16 * mt + (lane >> 2) + 8 * half;
                if (row >= M) continue;
                const float* c = acc[mt][nt] + 2 * half;
                float v0 = c[0] * sc0 + sh0;
                float v1 = c[1] * sc1 + sh1;
                if (do_relu) { v0 = fmaxf(v0, 0.f); v1 = fmaxf(v1, 0.f); }
                if (Ch) {
                    bf162 hi = __float22bfloat162_rn(make_float2(v0, v1));
                    float2 hf2 = __bfloat1622float2(hi);
                    bf162 lo = __float22bfloat162_rn(
                        make_float2(v0 - hf2.x, v1 - hf2.y));
                    *(bf162*)(Ch + (size_t)row * N + col) = hi;
                    *(bf162*)(Cl + (size_t)row * N + col) = lo;
                } else {
                    *(float2*)(Cf + (size_t)row * N + col) = make_float2(v0, v1);
                }
            }
        }
    }
}

// ---------------- split fp32 -> bf16 hi/lo planes ----------------
__global__ void split_planes(const float* __restrict__ x,
                             bf16* __restrict__ xh, bf16* __restrict__ xl,
                             int n4)
{
    int i = blockIdx.x * blockDim.x + threadIdx.x;
    if (i >= n4) return;
    float4 v = ((const float4*)x)[i];
    bf162 h0 = __float22bfloat162_rn(make_float2(v.x, v.y));
    bf162 h1 = __float22bfloat162_rn(make_float2(v.z, v.w));
    float2 f0 = __bfloat1622float2(h0);
    float2 f1 = __bfloat1622float2(h1);
    bf162 l0 = __float22bfloat162_rn(make_float2(v.x - f0.x, v.y - f0.y));
    bf162 l1 = __float22bfloat162_rn(make_float2(v.z - f1.x, v.w - f1.y));
    ((bf162*)xh)[i * 2]     = h0;
    ((bf162*)xh)[i * 2 + 1] = h1;
    ((bf162*)xl)[i * 2]     = l0;
    ((bf162*)xl)[i * 2 + 1] = l1;
}

// ---------------- graph aggregation ----------------
__global__ void compute_deg(const int* __restrict__ dst, float* __restrict__ deg, int E)
{
    int e = blockIdx.x * blockDim.x + threadIdx.x;
    if (e < E) atomicAdd(&deg[dst[e]], 1.0f);
}

__global__ void finalize_deg(float* __restrict__ deg, int n)
{
    int i = blockIdx.x * blockDim.x + threadIdx.x;
    if (i < n) deg[i] = 1.f / fmaxf(deg[i], 1.f);
}

// one warp per edge; reads hi/lo planes, reconstructs fp32, scaled v4 red
__global__ void scatter_mean(const bf16* __restrict__ hh, const bf16* __restrict__ hl,
                             const int* __restrict__ src, const int* __restrict__ dst,
                             const float* __restrict__ invdeg,
                             float* __restrict__ sum, int E, int D)
{
    const int warp = (blockIdx.x * blockDim.x + threadIdx.x) >> 5;
    const int lane = threadIdx.x & 31;
    if (warp >= E) return;
    const int s = src[warp];
    const int d = dst[warp];
    const float inv = invdeg[d];
    const uint2* ph = (const uint2*)(hh + (size_t)s * D);
    const uint2* pl = (const uint2*)(hl + (size_t)s * D);
    float* ds = sum + (size_t)d * D;
    const int D4 = D >> 2;
#pragma unroll 2
    for (int c = lane; c < D4; c += 32) {
        uint2 vh = ph[c];
        uint2 vl = pl[c];
        float2 a0 = __bfloat1622float2(*(const bf162*)&vh.x);
        float2 b0 = __bfloat1622float2(*(const bf162*)&vl.x);
        float2 a1 = __bfloat1622float2(*(const bf162*)&vh.y);
        float2 b1 = __bfloat1622float2(*(const bf162*)&vl.y);
        float x0 = (a0.x + b0.x) * inv;
        float x1 = (a0.y + b0.y) * inv;
        float x2 = (a1.x + b1.x) * inv;
        float x3 = (a1.y + b1.y) * inv;
        asm volatile("red.global.add.v4.f32 [%0], {%1,%2,%3,%4};"
                     :: "l"(ds + (size_t)c * 4),
                        "f"(x0), "f"(x1), "f"(x2), "f"(x3)
                     : "memory");
    }
}

// ---------------- launch helpers ----------------
static inline void launch_gemm(
    const bf16* A0h, const bf16* A0l, int K0,
    const bf16* A1h, const bf16* A1l, int K1,
    const bf16* W0h, const bf16* W0l, const bf16* W1h, const bf16* W1l,
    int M, int N,
    const float* bias, const float* bng, const float* bnb,
    const float* bnm, const float* bnv,
    int do_relu, float* Cf, bf16* Ch, bf16* Cl)
{
    dim3 grid((N + BN - 1) / BN, (M + BM - 1) / BM);
    gemm_bf16x3<<<grid, 256, GEMM_SMEM_BYTES>>>(
        A0h, A0l, K0, A1h, A1l, K1, W0h, W0l, W1h, W1l, M, N,
        bias, bng, bnb, bnm, bnv, do_relu, Cf, Ch, Cl);
}

extern "C" void kernel_launch(void* const* d_in, const int* in_sizes, int n_in,
                              void* d_out, int out_size)
{
    const float* structural = (const float*)d_in[0];
    const float* multimodal = (const float*)d_in[1];
    const int*   src        = (const int*)  d_in[2];
    const int*   dst        = (const int*)  d_in[3];
    const float* enc_w      = (const float*)d_in[4];
    const float* enc_b      = (const float*)d_in[5];
    const float* sage0_ws   = (const float*)d_in[6];
    const float* sage0_wn   = (const float*)d_in[7];
    const float* sage0_b    = (const float*)d_in[8];
    const float* bn0_g      = (const float*)d_in[9];
    const float* bn0_b      = (const float*)d_in[10];
    const float* bn0_m      = (const float*)d_in[11];
    const float* bn0_v      = (const float*)d_in[12];
    const float* sage1_ws   = (const float*)d_in[13];
    const float* sage1_wn   = (const float*)d_in[14];
    const float* sage1_b    = (const float*)d_in[15];
    const float* bn1_g      = (const float*)d_in[16];
    const float* bn1_b      = (const float*)d_in[17];
    const float* bn1_m      = (const float*)d_in[18];
    const float* bn1_v      = (const float*)d_in[19];
    const float* rel_w      = (const float*)d_in[20];
    const float* rel_b      = (const float*)d_in[21];
    const float* cls_w1     = (const float*)d_in[22];
    const float* cls_b1     = (const float*)d_in[23];
    const float* cls_w2     = (const float*)d_in[24];
    const float* cls_b2     = (const float*)d_in[25];
    float* out = (float*)d_out;

#define SYMADDR(var, sym) void* p_##var; cudaGetSymbolAddress(&p_##var, sym);
    SYMADDR(xsh, g_xsh) SYMADDR(xsl, g_xsl) SYMADDR(xmh, g_xmh) SYMADDR(xml, g_xml)
    SYMADDR(h0h, g_h0h) SYMADDR(h0l, g_h0l) SYMADDR(a0h, g_a0h) SYMADDR(a0l, g_a0l)
    SYMADDR(h1h, g_h1h) SYMADDR(h1l, g_h1l) SYMADDR(a1h, g_a1h) SYMADDR(a1l, g_a1l)
    SYMADDR(h2h, g_h2h) SYMADDR(h2l, g_h2l) SYMADDR(hfh, g_hfh) SYMADDR(hfl, g_hfl)
    SYMADDR(c1h, g_c1h) SYMADDR(c1l, g_c1l)
    SYMADDR(agg0, g_agg0) SYMADDR(agg1, g_agg1) SYMADDR(deg, g_deg)
    SYMADDR(wh, g_wh) SYMADDR(wl, g_wl)
#undef SYMADDR

    bf16* xsh = (bf16*)p_xsh; bf16* xsl = (bf16*)p_xsl;
    bf16* xmh = (bf16*)p_xmh; bf16* xml = (bf16*)p_xml;
    bf16* h0h = (bf16*)p_h0h; bf16* h0l = (bf16*)p_h0l;
    bf16* a0h = (bf16*)p_a0h; bf16* a0l = (bf16*)p_a0l;
    bf16* h1h = (bf16*)p_h1h; bf16* h1l = (bf16*)p_h1l;
    bf16* a1h = (bf16*)p_a1h; bf16* a1l = (bf16*)p_a1l;
    bf16* h2h = (bf16*)p_h2h; bf16* h2l = (bf16*)p_h2l;
    bf16* hfh = (bf16*)p_hfh; bf16* hfl = (bf16*)p_hfl;
    bf16* c1h = (bf16*)p_c1h; bf16* c1l = (bf16*)p_c1l;
    float* agg0 = (float*)p_agg0; float* agg1 = (float*)p_agg1;
    float* deg = (float*)p_deg;
    bf16* wh = (bf16*)p_wh; bf16* wl = (bf16*)p_wl;

    cudaFuncSetAttribute(gemm_bf16x3, cudaFuncAttributeMaxDynamicSharedMemorySize,
                         GEMM_SMEM_BYTES);

    const int M = N_NODES, E = N_EDGES;

    // zero atomic accumulators
    cudaMemsetAsync(deg,  0, (size_t)N_NODES * sizeof(float), 0);
    cudaMemsetAsync(agg0, 0, (size_t)N_NODES * 128 * sizeof(float), 0);
    cudaMemsetAsync(agg1, 0, (size_t)N_NODES * 256 * sizeof(float), 0);

    // degrees
    compute_deg<<<(E + 255) / 256, 256>>>(dst, deg, E);
    finalize_deg<<<(M + 255) / 256, 256>>>(deg, M);

    // split graph inputs and weights into bf16 hi/lo planes
    {
        int n4;
        n4 = (M * 128) / 4;
        split_planes<<<(n4 + 255) / 256, 256>>>(structural, xsh, xsl, n4);
        n4 = (M * 384) / 4;
        split_planes<<<(n4 + 255) / 256, 256>>>(multimodal, xmh, xml, n4);
        n4 = (512 * 128) / 4;
        split_planes<<<(n4 + 255) / 256, 256>>>(enc_w, wh + WOFF_ENC, wl + WOFF_ENC, n4);
        n4 = (128 * 256) / 4;
        split_planes<<<(n4 + 255) / 256, 256>>>(sage0_ws, wh + WOFF_S0S, wl + WOFF_S0S, n4);
        split_planes<<<(n4 + 255) / 256, 256>>>(sage0_wn, wh + WOFF_S0N, wl + WOFF_S0N, n4);
        n4 = (256 * 128) / 4;
        split_planes<<<(n4 + 255) / 256, 256>>>(sage1_ws, wh + WOFF_S1S, wl + WOFF_S1S, n4);
        split_planes<<<(n4 + 255) / 256, 256>>>(sage1_wn, wh + WOFF_S1N, wl + WOFF_S1N, n4);
        split_planes<<<(n4 + 255) / 256, 256>>>(rel_w, wh + WOFF_REL, wl + WOFF_REL, n4);
        n4 = (128 * 64) / 4;
        split_planes<<<(n4 + 255) / 256, 256>>>(cls_w1, wh + WOFF_C1, wl + WOFF_C1, n4);
        n4 = (64 * 32) / 4;
        split_planes<<<(n4 + 255) / 256, 256>>>(cls_w2, wh + WOFF_C2, wl + WOFF_C2, n4);
    }

    // h0 = relu([xs|xm] @ enc_w + enc_b)   -> planes
    launch_gemm(xsh, xsl, 128, xmh, xml, 384,
                wh + WOFF_ENC, wl + WOFF_ENC,
                wh + WOFF_ENC + 128 * 128, wl + WOFF_ENC + 128 * 128,
                M, 128, enc_b, nullptr, nullptr, nullptr, nullptr, 1,
                nullptr, h0h, h0l);

    // agg0 = mean_{src->dst} h0
    scatter_mean<<<(E * 32 + 255) / 256, 256>>>(h0h, h0l, src, dst, deg, agg0, E, 128);
    split_planes<<<((M * 128) / 4 + 255) / 256, 256>>>(agg0, a0h, a0l, (M * 128) / 4);

    // h1 = relu(bn0(h0 @ ws0 + agg0 @ wn0 + b0))
    launch_gemm(h0h, h0l, 128, a0h, a0l, 128,
                wh + WOFF_S0S, wl + WOFF_S0S, wh + WOFF_S0N, wl + WOFF_S0N,
                M, 256, sage0_b, bn0_g, bn0_b, bn0_m, bn0_v, 1,
                nullptr, h1h, h1l);

    // agg1 = mean_{src->dst} h1
    scatter_mean<<<(E * 32 + 255) / 256, 256>>>(h1h, h1l, src, dst, deg, agg1, E, 256);
    split_planes<<<((M * 256) / 4 + 255) / 256, 256>>>(agg1, a1h, a1l, (M * 256) / 4);

    // h2 = relu(bn1(h1 @ ws1 + agg1 @ wn1 + b1))
    launch_gemm(h1h, h1l, 256, a1h, a1l, 256,
                wh + WOFF_S1S, wl + WOFF_S1S, wh + WOFF_S1N, wl + WOFF_S1N,
                M, 128, sage1_b, bn1_g, bn1_b, bn1_m, bn1_v, 1,
                nullptr, h2h, h2l);

    // hf = relu([h0|h2] @ rel_w + rel_b)
    launch_gemm(h0h, h0l, 128, h2h, h2l, 128,
                wh + WOFF_REL, wl + WOFF_REL,
                wh + WOFF_REL + 128 * 128, wl + WOFF_REL + 128 * 128,
                M, 128, rel_b, nullptr, nullptr, nullptr, nullptr, 1,
                nullptr, hfh, hfl);

    // c1 = relu(hf @ cls_w1 + cls_b1)
    launch_gemm(hfh, hfl, 128, hfh, hfl, 0,
                wh + WOFF_C1, wl + WOFF_C1, wh + WOFF_C1, wl + WOFF_C1,
                M, 64, cls_b1, nullptr, nullptr, nullptr, nullptr, 1,
                nullptr, c1h, c1l);

    // out = c1 @ cls_w2 + cls_b2   (fp32)
    launch_gemm(c1h, c1l, 64, c1h, c1l, 0,
                wh + WOFF_C2, wl + WOFF_C2, wh + WOFF_C2, wl + WOFF_C2,
                M, 32, cls_b2, nullptr, nullptr, nullptr, nullptr, 0,
                out, nullptr, nullptr);
}

// round 6
// speedup vs baseline: 2.9882x; 1.0927x over previous
#include <cuda_runtime.h>
#include <cuda_bf16.h>
#include <math.h>
#include <stdint.h>

#define N_NODES 100000
#define N_EDGES 800000

typedef __nv_bfloat16  bf16;
typedef __nv_bfloat162 bf162;

// ---------------- scratch (device globals; no allocs allowed) ----------------
__device__ bf16 g_xsh[(size_t)N_NODES * 128], g_xsl[(size_t)N_NODES * 128];
__device__ bf16 g_xmh[(size_t)N_NODES * 384], g_xml[(size_t)N_NODES * 384];
__device__ bf16 g_h0h[(size_t)N_NODES * 128], g_h0l[(size_t)N_NODES * 128];
__device__ bf16 g_a0h[(size_t)N_NODES * 128], g_a0l[(size_t)N_NODES * 128];
__device__ bf16 g_h1h[(size_t)N_NODES * 256], g_h1l[(size_t)N_NODES * 256];
__device__ bf16 g_a1h[(size_t)N_NODES * 256], g_a1l[(size_t)N_NODES * 256];
__device__ bf16 g_h2h[(size_t)N_NODES * 128], g_h2l[(size_t)N_NODES * 128];
__device__ bf16 g_hfh[(size_t)N_NODES * 128], g_hfl[(size_t)N_NODES * 128];
__device__ bf16 g_c1h[(size_t)N_NODES * 64],  g_c1l[(size_t)N_NODES * 64];
__device__ bf16 g_wh[262144], g_wl[262144];
__device__ int g_counts[N_NODES];
__device__ int g_rowptr[N_NODES + 1];
__device__ int g_fill  [N_NODES];
__device__ int g_csr   [N_EDGES];

// weight plane offsets (elements)
#define WOFF_ENC 0
#define WOFF_S0S 65536
#define WOFF_S0N 98304
#define WOFF_S1S 131072
#define WOFF_S1N 163840
#define WOFF_REL 196608
#define WOFF_C1  229376
#define WOFF_C2  237568

// ---------------- bf16x3 tensor-core GEMM (unchanged from R4, passing) --------
#define BM 128
#define BN 64
#define BK 32
#define A_STRIDE 40
#define B_STRIDE 72
#define A_PLANE (BM * A_STRIDE)
#define B_PLANE (BK * B_STRIDE)
#define STAGE_ELEMS (2 * A_PLANE + 2 * B_PLANE)
#define GEMM_SMEM_BYTES (2 * STAGE_ELEMS * 2)

__device__ __forceinline__ void cp16(uint32_t dst, const void* src, bool pred) {
    asm volatile("cp.async.cg.shared.global [%0], [%1], 16, %2;"
                 :: "r"(dst), "l"(src), "r"(pred ? 16 : 0));
}

#define LDMX4(r, addr)                                                          \
    asm volatile("ldmatrix.sync.aligned.m8n8.x4.shared.b16 {%0,%1,%2,%3},[%4];" \
                 : "=r"((r)[0]), "=r"((r)[1]), "=r"((r)[2]), "=r"((r)[3])       \
                 : "r"(addr))

#define LDMX4T(r, addr)                                                         \
    asm volatile("ldmatrix.sync.aligned.m8n8.x4.trans.shared.b16 "              \
                 "{%0,%1,%2,%3},[%4];"                                          \
                 : "=r"((r)[0]), "=r"((r)[1]), "=r"((r)[2]), "=r"((r)[3])       \
                 : "r"(addr))

#define MMA_BF16(acc, a, b0, b1)                                                \
    asm volatile(                                                               \
        "mma.sync.aligned.m16n8k16.row.col.f32.bf16.bf16.f32 "                  \
        "{%0,%1,%2,%3},{%4,%5,%6,%7},{%8,%9},{%0,%1,%2,%3};"                    \
        : "+f"((acc)[0]), "+f"((acc)[1]), "+f"((acc)[2]), "+f"((acc)[3])        \
        : "r"((a)[0]), "r"((a)[1]), "r"((a)[2]), "r"((a)[3]),                   \
          "r"(b0), "r"(b1))

__global__ __launch_bounds__(256) void gemm_bf16x3(
    const bf16* __restrict__ A0h, const bf16* __restrict__ A0l, int K0,
    const bf16* __restrict__ A1h, const bf16* __restrict__ A1l, int K1,
    const bf16* __restrict__ W0h, const bf16* __restrict__ W0l,
    const bf16* __restrict__ W1h, const bf16* __restrict__ W1l,
    int M, int N,
    const float* __restrict__ bias,
    const float* __restrict__ bng, const float* __restrict__ bnb,
    const float* __restrict__ bnm, const float* __restrict__ bnv,
    int do_relu,
    float* __restrict__ Cf, bf16* __restrict__ Ch, bf16* __restrict__ Cl)
{
    extern __shared__ bf16 smem[];
    const uint32_t smem_u32 = (uint32_t)__cvta_generic_to_shared(smem);

    const int tid  = threadIdx.x;
    const int lane = tid & 31;
    const int wid  = tid >> 5;
    const int wm   = (wid & 3) * 32;
    const int wn   = (wid >> 2) * 32;
    const int brow = blockIdx.y * BM;
    const int bcol = blockIdx.x * BN;
    const int K = K0 + K1;
    const int T = K / BK;

    const int a_row = tid >> 1;
    const int a_k   = (tid & 1) * 16;
    const int a_gr  = brow + a_row;
    const bool a_ok = (a_gr < M);
    const int b_k = tid >> 3;
    const int b_n = (tid & 7) * 8;

    const int a_lm = (wm + (lane & 15)) * A_STRIDE + (lane >> 4) * 8;
    const int b_lm = ((lane & 7) + ((lane >> 3) & 1) * 8) * B_STRIDE
                     + wn + (lane >> 4) * 8;

    float acc[2][4][4];
#pragma unroll
    for (int mt = 0; mt < 2; mt++)
#pragma unroll
        for (int nt = 0; nt < 4; nt++)
#pragma unroll
            for (int i = 0; i < 4; i++) acc[mt][nt][i] = 0.f;

#define LOAD_TILE(t, st) do {                                                     \
        const int kt_ = (t) * BK;                                                 \
        { int gk0 = kt_ + a_k;                                                    \
          const bf16 *sph, *spl;                                                  \
          if (gk0 < K0) { sph = A0h + (size_t)a_gr * K0 + gk0;                    \
                          spl = A0l + (size_t)a_gr * K0 + gk0; }                  \
          else          { sph = A1h + (size_t)a_gr * K1 + (gk0 - K0);             \
                          spl = A1l + (size_t)a_gr * K1 + (gk0 - K0); }           \
          uint32_t dh = smem_u32 +                                                \
              ((st) * STAGE_ELEMS + a_row * A_STRIDE + a_k) * 2;                  \
          cp16(dh,      sph,     a_ok);                                           \
          cp16(dh + 16, sph + 8, a_ok);                                           \
          uint32_t dl = dh + A_PLANE * 2;                                         \
          cp16(dl,      spl,     a_ok);                                           \
          cp16(dl + 16, spl + 8, a_ok);                                           \
        }                                                                         \
        { int gk = kt_ + b_k;                                                     \
          const bf16 *wph, *wpl; int kk2;                                         \
          if (gk < K0) { wph = W0h; wpl = W0l; kk2 = gk; }                        \
          else         { wph = W1h; wpl = W1l; kk2 = gk - K0; }                   \
          int n0 = bcol + b_n;                                                    \
          bool ok = (n0 < N);                                                     \
          uint32_t dbh = smem_u32 +                                               \
              ((st) * STAGE_ELEMS + 2 * A_PLANE + b_k * B_STRIDE + b_n) * 2;      \
          cp16(dbh,               wph + (size_t)kk2 * N + n0, ok);                \
          cp16(dbh + B_PLANE * 2, wpl + (size_t)kk2 * N + n0, ok);                \
        }                                                                         \
        asm volatile("cp.async.commit_group;");                                   \
    } while (0)

    LOAD_TILE(0, 0);

    for (int t = 0; t < T; ++t) {
        const int st = t & 1;
        if (t + 1 < T) {
            LOAD_TILE(t + 1, st ^ 1);
            asm volatile("cp.async.wait_group 1;");
        } else {
            asm volatile("cp.async.wait_group 0;");
        }
        __syncthreads();

        const uint32_t base = smem_u32 + st * STAGE_ELEMS * 2;
#pragma unroll
        for (int k16 = 0; k16 < 2; k16++) {
            uint32_t ah[2][4], al[2][4], bh[2][4], bl[2][4];
#pragma unroll
            for (int mt = 0; mt < 2; mt++) {
                uint32_t ad = base + (a_lm + mt * 16 * A_STRIDE + k16 * 16) * 2;
                LDMX4(ah[mt], ad);
                LDMX4(al[mt], ad + A_PLANE * 2);
            }
#pragma unroll
            for (int p = 0; p < 2; p++) {
                uint32_t bd = base + (2 * A_PLANE + b_lm + p * 16
                                      + k16 * 16 * B_STRIDE) * 2;
                LDMX4T(bh[p], bd);
                LDMX4T(bl[p], bd + B_PLANE * 2);
            }
#pragma unroll
            for (int mt = 0; mt < 2; mt++)
#pragma unroll
                for (int nt = 0; nt < 4; nt++) {
                    const int p = nt >> 1, q = (nt & 1) * 2;
                    MMA_BF16(acc[mt][nt], al[mt], bh[p][q], bh[p][q + 1]);
                    MMA_BF16(acc[mt][nt], ah[mt], bl[p][q], bl[p][q + 1]);
                    MMA_BF16(acc[mt][nt], ah[mt], bh[p][q], bh[p][q + 1]);
                }
        }
        __syncthreads();
    }

#pragma unroll
    for (int nt = 0; nt < 4; nt++) {
        const int col = bcol + wn + 8 * nt + 2 * (lane & 3);
        if (col >= N) continue;
        float sc0 = 1.f, sh0 = 0.f, sc1 = 1.f, sh1 = 0.f;
        if (bias) { sh0 = bias[col]; sh1 = bias[col + 1]; }
        if (bng) {
            float s0 = bng[col]     * rsqrtf(bnv[col]     + 1e-5f);
            float s1 = bng[col + 1] * rsqrtf(bnv[col + 1] + 1e-5f);
            sh0 = (sh0 - bnm[col])     * s0 + bnb[col];
            sh1 = (sh1 - bnm[col + 1]) * s1 + bnb[col + 1];
            sc0 = s0; sc1 = s1;
        }
#pragma unroll
        for (int mt = 0; mt < 2; mt++) {
#pragma unroll
            for (int half = 0; half < 2; half++) {
                const int row = brow + wm + 16 * mt + (lane >> 2) + 8 * half;
                if (row >= M) continue;
                const float* c = acc[mt][nt] + 2 * half;
                float v0 = c[0] * sc0 + sh0;
                float v1 = c[1] * sc1 + sh1;
                if (do_relu) { v0 = fmaxf(v0, 0.f); v1 = fmaxf(v1, 0.f); }
                if (Ch) {
                    bf162 hi = __float22bfloat162_rn(make_float2(v0, v1));
                    float2 hf2 = __bfloat1622float2(hi);
                    bf162 lo = __float22bfloat162_rn(
                        make_float2(v0 - hf2.x, v1 - hf2.y));
                    *(bf162*)(Ch + (size_t)row * N + col) = hi;
                    *(bf162*)(Cl + (size_t)row * N + col) = lo;
                } else {
                    *(float2*)(Cf + (size_t)row * N + col) = make_float2(v0, v1);
                }
            }
        }
    }
}

// ---------------- split fp32 -> bf16 hi/lo planes ----------------
__global__ void split_planes(const float* __restrict__ x,
                             bf16* __restrict__ xh, bf16* __restrict__ xl, int n4)
{
    int i = blockIdx.x * blockDim.x + threadIdx.x;
    if (i >= n4) return;
    float4 v = ((const float4*)x)[i];
    bf162 h0 = __float22bfloat162_rn(make_float2(v.x, v.y));
    bf162 h1 = __float22bfloat162_rn(make_float2(v.z, v.w));
    float2 f0 = __bfloat1622float2(h0);
    float2 f1 = __bfloat1622float2(h1);
    bf162 l0 = __float22bfloat162_rn(make_float2(v.x - f0.x, v.y - f0.y));
    bf162 l1 = __float22bfloat162_rn(make_float2(v.z - f1.x, v.w - f1.y));
    ((bf162*)xh)[i * 2]     = h0;
    ((bf162*)xh)[i * 2 + 1] = h1;
    ((bf162*)xl)[i * 2]     = l0;
    ((bf162*)xl)[i * 2 + 1] = l1;
}

// ---------------- CSR construction ----------------
__global__ void count_deg(const int* __restrict__ dst, int* __restrict__ counts, int E)
{
    int e = blockIdx.x * blockDim.x + threadIdx.x;
    if (e < E) atomicAdd(&counts[dst[e]], 1);
}

// single-block exclusive scan over counts -> rowptr (+fill copy)
__global__ __launch_bounds__(1024) void scan_counts(
    const int* __restrict__ counts, int* __restrict__ rowptr,
    int* __restrict__ fill, int n)
{
    __shared__ int part[1024];
    const int tid = threadIdx.x;
    const int chunk = (n + 1023) / 1024;
    const int begin = min(tid * chunk, n);
    const int end   = min(begin + chunk, n);
    int s = 0;
    for (int i = begin; i < end; i++) s += counts[i];
    part[tid] = s;
    __syncthreads();
    for (int off = 1; off < 1024; off <<= 1) {
        int v = (tid >= off) ? part[tid - off] : 0;
        __syncthreads();
        part[tid] += v;
        __syncthreads();
    }
    int pre = (tid == 0) ? 0 : part[tid - 1];
    for (int i = begin; i < end; i++) {
        rowptr[i] = pre;
        fill[i]   = pre;
        pre += counts[i];
    }
    if (end == n && begin <= n) rowptr[n] = pre;
}

__global__ void fill_csr(const int* __restrict__ src, const int* __restrict__ dst,
                         int* __restrict__ fill, int* __restrict__ csr, int E)
{
    int e = blockIdx.x * blockDim.x + threadIdx.x;
    if (e < E) {
        int pos = atomicAdd(&fill[dst[e]], 1);
        csr[pos] = src[e];
    }
}

// ---------------- CSR gather mean: warp per dst node, writes planes ----------
__global__ void gather_mean(const bf16* __restrict__ hh, const bf16* __restrict__ hl,
                            const int* __restrict__ csr, const int* __restrict__ rowptr,
                            bf16* __restrict__ oh, bf16* __restrict__ ol,
                            int Nn, int D)
{
    const int warp = (blockIdx.x * blockDim.x + threadIdx.x) >> 5;
    const int lane = threadIdx.x & 31;
    if (warp >= Nn) return;
    const int e0 = rowptr[warp];
    const int e1 = rowptr[warp + 1];
    const float inv = 1.f / (float)max(e1 - e0, 1);
    const int nseg = D >> 7;            // 128 cols per segment
    float acc[8];                       // up to 2 segs * 4 cols/lane
#pragma unroll
    for (int i = 0; i < 8; i++) acc[i] = 0.f;

    for (int e = e0; e < e1; e++) {
        const int s = csr[e];
        const bf16* rh = hh + (size_t)s * D + lane * 4;
        const bf16* rl = hl + (size_t)s * D + lane * 4;
#pragma unroll
        for (int g = 0; g < 2; g++) {
            if (g < nseg) {
                uint2 vh = *(const uint2*)(rh + g * 128);
                uint2 vl = *(const uint2*)(rl + g * 128);
                float2 a0 = __bfloat1622float2(*(const bf162*)&vh.x);
                float2 a1 = __bfloat1622float2(*(const bf162*)&vh.y);
                float2 b0 = __bfloat1622float2(*(const bf162*)&vl.x);
                float2 b1 = __bfloat1622float2(*(const bf162*)&vl.y);
                acc[g * 4 + 0] += a0.x + b0.x;
                acc[g * 4 + 1] += a0.y + b0.y;
                acc[g * 4 + 2] += a1.x + b1.x;
                acc[g * 4 + 3] += a1.y + b1.y;
            }
        }
    }

#pragma unroll
    for (int g = 0; g < 2; g++) {
        if (g < nseg) {
            float v0 = acc[g * 4 + 0] * inv;
            float v1 = acc[g * 4 + 1] * inv;
            float v2 = acc[g * 4 + 2] * inv;
            float v3 = acc[g * 4 + 3] * inv;
            bf162 h0 = __float22bfloat162_rn(make_float2(v0, v1));
            bf162 h1 = __float22bfloat162_rn(make_float2(v2, v3));
            float2 f0 = __bfloat1622float2(h0);
            float2 f1 = __bfloat1622float2(h1);
            bf162 l0 = __float22bfloat162_rn(make_float2(v0 - f0.x, v1 - f0.y));
            bf162 l1 = __float22bfloat162_rn(make_float2(v2 - f1.x, v3 - f1.y));
            uint2 wh_, wl_;
            wh_.x = *(uint32_t*)&h0; wh_.y = *(uint32_t*)&h1;
            wl_.x = *(uint32_t*)&l0; wl_.y = *(uint32_t*)&l1;
            *(uint2*)(oh + (size_t)warp * D + g * 128 + lane * 4) = wh_;
            *(uint2*)(ol + (size_t)warp * D + g * 128 + lane * 4) = wl_;
        }
    }
}

// ---------------- launch helpers ----------------
static inline void launch_gemm(
    const bf16* A0h, const bf16* A0l, int K0,
    const bf16* A1h, const bf16* A1l, int K1,
    const bf16* W0h, const bf16* W0l, const bf16* W1h, const bf16* W1l,
    int M, int N,
    const float* bias, const float* bng, const float* bnb,
    const float* bnm, const float* bnv,
    int do_relu, float* Cf, bf16* Ch, bf16* Cl)
{
    dim3 grid((N + BN - 1) / BN, (M + BM - 1) / BM);
    gemm_bf16x3<<<grid, 256, GEMM_SMEM_BYTES>>>(
        A0h, A0l, K0, A1h, A1l, K1, W0h, W0l, W1h, W1l, M, N,
        bias, bng, bnb, bnm, bnv, do_relu, Cf, Ch, Cl);
}

extern "C" void kernel_launch(void* const* d_in, const int* in_sizes, int n_in,
                              void* d_out, int out_size)
{
    const float* structural = (const float*)d_in[0];
    const float* multimodal = (const float*)d_in[1];
    const int*   src        = (const int*)  d_in[2];
    const int*   dst        = (const int*)  d_in[3];
    const float* enc_w      = (const float*)d_in[4];
    const float* enc_b      = (const float*)d_in[5];
    const float* sage0_ws   = (const float*)d_in[6];
    const float* sage0_wn   = (const float*)d_in[7];
    const float* sage0_b    = (const float*)d_in[8];
    const float* bn0_g      = (const float*)d_in[9];
    const float* bn0_b      = (const float*)d_in[10];
    const float* bn0_m      = (const float*)d_in[11];
    const float* bn0_v      = (const float*)d_in[12];
    const float* sage1_ws   = (const float*)d_in[13];
    const float* sage1_wn   = (const float*)d_in[14];
    const float* sage1_b    = (const float*)d_in[15];
    const float* bn1_g      = (const float*)d_in[16];
    const float* bn1_b      = (const float*)d_in[17];
    const float* bn1_m      = (const float*)d_in[18];
    const float* bn1_v      = (const float*)d_in[19];
    const float* rel_w      = (const float*)d_in[20];
    const float* rel_b      = (const float*)d_in[21];
    const float* cls_w1     = (const float*)d_in[22];
    const float* cls_b1     = (const float*)d_in[23];
    const float* cls_w2     = (const float*)d_in[24];
    const float* cls_b2     = (const float*)d_in[25];
    float* out = (float*)d_out;

#define SYMADDR(var, sym) void* p_##var; cudaGetSymbolAddress(&p_##var, sym);
    SYMADDR(xsh, g_xsh) SYMADDR(xsl, g_xsl) SYMADDR(xmh, g_xmh) SYMADDR(xml, g_xml)
    SYMADDR(h0h, g_h0h) SYMADDR(h0l, g_h0l) SYMADDR(a0h, g_a0h) SYMADDR(a0l, g_a0l)
    SYMADDR(h1h, g_h1h) SYMADDR(h1l, g_h1l) SYMADDR(a1h, g_a1h) SYMADDR(a1l, g_a1l)
    SYMADDR(h2h, g_h2h) SYMADDR(h2l, g_h2l) SYMADDR(hfh, g_hfh) SYMADDR(hfl, g_hfl)
    SYMADDR(c1h, g_c1h) SYMADDR(c1l, g_c1l)
    SYMADDR(wh, g_wh) SYMADDR(wl, g_wl)
    SYMADDR(counts, g_counts) SYMADDR(rowptr, g_rowptr)
    SYMADDR(fill, g_fill) SYMADDR(csr, g_csr)
#undef SYMADDR

    bf16* xsh = (bf16*)p_xsh; bf16* xsl = (bf16*)p_xsl;
    bf16* xmh = (bf16*)p_xmh; bf16* xml = (bf16*)p_xml;
    bf16* h0h = (bf16*)p_h0h; bf16* h0l = (bf16*)p_h0l;
    bf16* a0h = (bf16*)p_a0h; bf16* a0l = (bf16*)p_a0l;
    bf16* h1h = (bf16*)p_h1h; bf16* h1l = (bf16*)p_h1l;
    bf16* a1h = (bf16*)p_a1h; bf16* a1l = (bf16*)p_a1l;
    bf16* h2h = (bf16*)p_h2h; bf16* h2l = (bf16*)p_h2l;
    bf16* hfh = (bf16*)p_hfh; bf16* hfl = (bf16*)p_hfl;
    bf16* c1h = (bf16*)p_c1h; bf16* c1l = (bf16*)p_c1l;
    bf16* wh = (bf16*)p_wh; bf16* wl = (bf16*)p_wl;
    int* counts = (int*)p_counts; int* rowptr = (int*)p_rowptr;
    int* fill   = (int*)p_fill;   int* csr    = (int*)p_csr;

    cudaFuncSetAttribute(gemm_bf16x3, cudaFuncAttributeMaxDynamicSharedMemorySize,
                         GEMM_SMEM_BYTES);

    const int M = N_NODES, E = N_EDGES;

    // ---- CSR build (same graph used by both layers) ----
    cudaMemsetAsync(counts, 0, N_NODES * sizeof(int), 0);
    count_deg<<<(E + 255) / 256, 256>>>(dst, counts, E);
    scan_counts<<<1, 1024>>>(counts, rowptr, fill, M);
    fill_csr<<<(E + 255) / 256, 256>>>(src, dst, fill, csr, E);

    // ---- split graph inputs & weights into bf16 hi/lo planes ----
    {
        int n4;
        n4 = (M * 128) / 4;
        split_planes<<<(n4 + 255) / 256, 256>>>(structural, xsh, xsl, n4);
        n4 = (M * 384) / 4;
        split_planes<<<(n4 + 255) / 256, 256>>>(multimodal, xmh, xml, n4);
        n4 = (512 * 128) / 4;
        split_planes<<<(n4 + 255) / 256, 256>>>(enc_w, wh + WOFF_ENC, wl + WOFF_ENC, n4);
        n4 = (128 * 256) / 4;
        split_planes<<<(n4 + 255) / 256, 256>>>(sage0_ws, wh + WOFF_S0S, wl + WOFF_S0S, n4);
        split_planes<<<(n4 + 255) / 256, 256>>>(sage0_wn, wh + WOFF_S0N, wl + WOFF_S0N, n4);
        n4 = (256 * 128) / 4;
        split_planes<<<(n4 + 255) / 256, 256>>>(sage1_ws, wh + WOFF_S1S, wl + WOFF_S1S, n4);
        split_planes<<<(n4 + 255) / 256, 256>>>(sage1_wn, wh + WOFF_S1N, wl + WOFF_S1N, n4);
        split_planes<<<(n4 + 255) / 256, 256>>>(rel_w, wh + WOFF_REL, wl + WOFF_REL, n4);
        n4 = (128 * 64) / 4;
        split_planes<<<(n4 + 255) / 256, 256>>>(cls_w1, wh + WOFF_C1, wl + WOFF_C1, n4);
        n4 = (64 * 32) / 4;
        split_planes<<<(n4 + 255) / 256, 256>>>(cls_w2, wh + WOFF_C2, wl + WOFF_C2, n4);
    }

    // h0 = relu([xs|xm] @ enc_w + enc_b)
    launch_gemm(xsh, xsl, 128, xmh, xml, 384,
                wh + WOFF_ENC, wl + WOFF_ENC,
                wh + WOFF_ENC + 128 * 128, wl + WOFF_ENC + 128 * 128,
                M, 128, enc_b, nullptr, nullptr, nullptr, nullptr, 1,
                nullptr, h0h, h0l);

    // agg0 = mean h0  (CSR gather, writes planes directly)
    gather_mean<<<(M * 32 + 255) / 256, 256>>>(h0h, h0l, csr, rowptr,
                                               a0h, a0l, M, 128);

    // h1 = relu(bn0(h0 @ ws0 + agg0 @ wn0 + b0))
    launch_gemm(h0h, h0l, 128, a0h, a0l, 128,
                wh + WOFF_S0S, wl + WOFF_S0S, wh + WOFF_S0N, wl + WOFF_S0N,
                M, 256, sage0_b, bn0_g, bn0_b, bn0_m, bn0_v, 1,
                nullptr, h1h, h1l);

    // agg1 = mean h1
    gather_mean<<<(M * 32 + 255) / 256, 256>>>(h1h, h1l, csr, rowptr,
                                               a1h, a1l, M, 256);

    // h2 = relu(bn1(h1 @ ws1 + agg1 @ wn1 + b1))
    launch_gemm(h1h, h1l, 256, a1h, a1l, 256,
                wh + WOFF_S1S, wl + WOFF_S1S, wh + WOFF_S1N, wl + WOFF_S1N,
                M, 128, sage1_b, bn1_g, bn1_b, bn1_m, bn1_v, 1,
                nullptr, h2h, h2l);

    // hf = relu([h0|h2] @ rel_w + rel_b)
    launch_gemm(h0h, h0l, 128, h2h, h2l, 128,
                wh + WOFF_REL, wl + WOFF_REL,
                wh + WOFF_REL + 128 * 128, wl + WOFF_REL + 128 * 128,
                M, 128, rel_b, nullptr, nullptr, nullptr, nullptr, 1,
                nullptr, hfh, hfl);

    // c1 = relu(hf @ cls_w1 + cls_b1)
    launch_gemm(hfh, hfl, 128, hfh, hfl, 0,
                wh + WOFF_C1, wl + WOFF_C1, wh + WOFF_C1, wl + WOFF_C1,
                M, 64, cls_b1, nullptr, nullptr, nullptr, nullptr, 1,
                nullptr, c1h, c1l);

    // out = c1 @ cls_w2 + cls_b2   (fp32)
    launch_gemm(c1h, c1l, 64, c1h, c1l, 0,
                wh + WOFF_C2, wl + WOFF_C2, wh + WOFF_C2, wl + WOFF_C2,
                M, 32, cls_b2, nullptr, nullptr, nullptr, nullptr, 0,
                out, nullptr, nullptr);
}

// round 7
// speedup vs baseline: 3.1746x; 1.0624x over previous
#include <cuda_runtime.h>
#include <cuda_bf16.h>
#include <math.h>
#include <stdint.h>

#define N_NODES 100000
#define N_EDGES 800000

typedef __nv_bfloat16  bf16;
typedef __nv_bfloat162 bf162;

// ---------------- scratch (device globals; no allocs allowed) ----------------
__device__ bf16 g_xsh[(size_t)N_NODES * 128], g_xsl[(size_t)N_NODES * 128];
__device__ bf16 g_xmh[(size_t)N_NODES * 384], g_xml[(size_t)N_NODES * 384];
__device__ bf16 g_h0h[(size_t)N_NODES * 128], g_h0l[(size_t)N_NODES * 128];
__device__ bf16 g_a0h[(size_t)N_NODES * 128], g_a0l[(size_t)N_NODES * 128];
__device__ bf16 g_h1h[(size_t)N_NODES * 256], g_h1l[(size_t)N_NODES * 256];
__device__ bf16 g_a1h[(size_t)N_NODES * 256], g_a1l[(size_t)N_NODES * 256];
__device__ bf16 g_h2h[(size_t)N_NODES * 128], g_h2l[(size_t)N_NODES * 128];
__device__ bf16 g_hfh[(size_t)N_NODES * 128], g_hfl[(size_t)N_NODES * 128];
__device__ bf16 g_c1h[(size_t)N_NODES * 64],  g_c1l[(size_t)N_NODES * 64];
__device__ bf16 g_wh[262144], g_wl[262144];
__device__ int g_counts[N_NODES];
__device__ int g_rowptr[N_NODES + 1];
__device__ int g_fill  [N_NODES];
__device__ int g_csr   [N_EDGES];

// weight plane offsets (elements)
#define WOFF_ENC 0
#define WOFF_S0S 65536
#define WOFF_S0N 98304
#define WOFF_S1S 131072
#define WOFF_S1N 163840
#define WOFF_REL 196608
#define WOFF_C1  229376
#define WOFF_C2  237568

// ---------------- bf16x3 tensor-core GEMM, templated block width ----------------
#define BM 128
#define BK 32
#define A_STRIDE 40
#define A_PLANE (BM * A_STRIDE)

__device__ __forceinline__ void cp16(uint32_t dst, const void* src, bool pred) {
    asm volatile("cp.async.cg.shared.global [%0], [%1], 16, %2;"
                 :: "r"(dst), "l"(src), "r"(pred ? 16 : 0));
}

#define LDMX4(r, addr)                                                          \
    asm volatile("ldmatrix.sync.aligned.m8n8.x4.shared.b16 {%0,%1,%2,%3},[%4];" \
                 : "=r"((r)[0]), "=r"((r)[1]), "=r"((r)[2]), "=r"((r)[3])       \
                 : "r"(addr))

#define LDMX4T(r, addr)                                                         \
    asm volatile("ldmatrix.sync.aligned.m8n8.x4.trans.shared.b16 "              \
                 "{%0,%1,%2,%3},[%4];"                                          \
                 : "=r"((r)[0]), "=r"((r)[1]), "=r"((r)[2]), "=r"((r)[3])       \
                 : "r"(addr))

#define MMA_BF16(acc, a, b0, b1)                                                \
    asm volatile(                                                               \
        "mma.sync.aligned.m16n8k16.row.col.f32.bf16.bf16.f32 "                  \
        "{%0,%1,%2,%3},{%4,%5,%6,%7},{%8,%9},{%0,%1,%2,%3};"                    \
        : "+f"((acc)[0]), "+f"((acc)[1]), "+f"((acc)[2]), "+f"((acc)[3])        \
        : "r"((a)[0]), "r"((a)[1]), "r"((a)[2]), "r"((a)[3]),                   \
          "r"(b0), "r"(b1))

template<int BN_>
__global__ __launch_bounds__(256) void gemm_bf16x3(
    const bf16* __restrict__ A0h, const bf16* __restrict__ A0l, int K0,
    const bf16* __restrict__ A1h, const bf16* __restrict__ A1l, int K1,
    const bf16* __restrict__ W0h, const bf16* __restrict__ W0l,
    const bf16* __restrict__ W1h, const bf16* __restrict__ W1l,
    int M, int N,
    const float* __restrict__ bias,
    const float* __restrict__ bng, const float* __restrict__ bnb,
    const float* __restrict__ bnm, const float* __restrict__ bnv,
    int do_relu,
    float* __restrict__ Cf, bf16* __restrict__ Ch, bf16* __restrict__ Cl)
{
    constexpr int B_STRIDE = BN_ + 8;
    constexpr int B_PLANE  = BK * B_STRIDE;
    constexpr int STAGE_ELEMS = 2 * A_PLANE + 2 * B_PLANE;
    constexpr int WARP_N = BN_ / 2;        // warp tile cols
    constexpr int NT = WARP_N / 8;         // n8 tiles per warp
    constexpr int P  = WARP_N / 16;        // LDMX4T groups per plane
    constexpr int NCP = BN_ / 64;          // 16B chunks per thread per plane (B loader)

    extern __shared__ bf16 smem[];
    const uint32_t smem_u32 = (uint32_t)__cvta_generic_to_shared(smem);

    const int tid  = threadIdx.x;
    const int lane = tid & 31;
    const int wid  = tid >> 5;
    const int wm   = (wid & 3) * 32;
    const int wn   = (wid >> 2) * WARP_N;
    const int brow = blockIdx.y * BM;
    const int bcol = blockIdx.x * BN_;
    const int K = K0 + K1;
    const int T = K / BK;

    const int a_row = tid >> 1;
    const int a_k   = (tid & 1) * 16;
    const int a_gr  = brow + a_row;
    const bool a_ok = (a_gr < M);
    const int b_k  = tid >> 3;
    const int b_n0 = (tid & 7) * (BN_ / 8);

    const int a_lm = (wm + (lane & 15)) * A_STRIDE + (lane >> 4) * 8;
    const int b_lm = ((lane & 7) + ((lane >> 3) & 1) * 8) * B_STRIDE
                     + wn + (lane >> 4) * 8;

    float acc[2][NT][4];
#pragma unroll
    for (int mt = 0; mt < 2; mt++)
#pragma unroll
        for (int nt = 0; nt < NT; nt++)
#pragma unroll
            for (int i = 0; i < 4; i++) acc[mt][nt][i] = 0.f;

#define LOAD_TILE(t, st) do {                                                     \
        const int kt_ = (t) * BK;                                                 \
        { int gk0 = kt_ + a_k;                                                    \
          const bf16 *sph, *spl;                                                  \
          if (gk0 < K0) { sph = A0h + (size_t)a_gr * K0 + gk0;                    \
                          spl = A0l + (size_t)a_gr * K0 + gk0; }                  \
          else          { sph = A1h + (size_t)a_gr * K1 + (gk0 - K0);             \
                          spl = A1l + (size_t)a_gr * K1 + (gk0 - K0); }           \
          uint32_t dh = smem_u32 +                                                \
              ((st) * STAGE_ELEMS + a_row * A_STRIDE + a_k) * 2;                  \
          cp16(dh,      sph,     a_ok);                                           \
          cp16(dh + 16, sph + 8, a_ok);                                           \
          uint32_t dl = dh + A_PLANE * 2;                                         \
          cp16(dl,      spl,     a_ok);                                           \
          cp16(dl + 16, spl + 8, a_ok);                                           \
        }                                                                         \
        { int gk = kt_ + b_k;                                                     \
          const bf16 *wph, *wpl; int kk2;                                         \
          if (gk < K0) { wph = W0h; wpl = W0l; kk2 = gk; }                        \
          else         { wph = W1h; wpl = W1l; kk2 = gk - K0; }                   \
          uint32_t dbh = smem_u32 +                                               \
              ((st) * STAGE_ELEMS + 2 * A_PLANE + b_k * B_STRIDE + b_n0) * 2;     \
          _Pragma("unroll")                                                       \
          for (int cc = 0; cc < NCP; cc++) {                                      \
              int n0 = bcol + b_n0 + cc * 8;                                      \
              bool ok = (n0 < N);                                                 \
              cp16(dbh + cc * 16,               wph + (size_t)kk2 * N + n0, ok);  \
              cp16(dbh + cc * 16 + B_PLANE * 2, wpl + (size_t)kk2 * N + n0, ok);  \
          }                                                                       \
        }                                                                         \
        asm volatile("cp.async.commit_group;");                                   \
    } while (0)

    LOAD_TILE(0, 0);

    for (int t = 0; t < T; ++t) {
        const int st = t & 1;
        if (t + 1 < T) {
            LOAD_TILE(t + 1, st ^ 1);
            asm volatile("cp.async.wait_group 1;");
        } else {
            asm volatile("cp.async.wait_group 0;");
        }
        __syncthreads();

        const uint32_t base = smem_u32 + st * STAGE_ELEMS * 2;
#pragma unroll
        for (int k16 = 0; k16 < 2; k16++) {
            uint32_t ah[2][4], al[2][4], bh[P][4], bl[P][4];
#pragma unroll
            for (int mt = 0; mt < 2; mt++) {
                uint32_t ad = base + (a_lm + mt * 16 * A_STRIDE + k16 * 16) * 2;
                LDMX4(ah[mt], ad);
                LDMX4(al[mt], ad + A_PLANE * 2);
            }
#pragma unroll
            for (int p = 0; p < P; p++) {
                uint32_t bd = base + (2 * A_PLANE + b_lm + p * 16
                                      + k16 * 16 * B_STRIDE) * 2;
                LDMX4T(bh[p], bd);
                LDMX4T(bl[p], bd + B_PLANE * 2);
            }
#pragma unroll
            for (int mt = 0; mt < 2; mt++)
#pragma unroll
                for (int nt = 0; nt < NT; nt++) {
                    const int p = nt >> 1, q = (nt & 1) * 2;
                    MMA_BF16(acc[mt][nt], al[mt], bh[p][q], bh[p][q + 1]);
                    MMA_BF16(acc[mt][nt], ah[mt], bl[p][q], bl[p][q + 1]);
                    MMA_BF16(acc[mt][nt], ah[mt], bh[p][q], bh[p][q + 1]);
                }
        }
        __syncthreads();
    }

#pragma unroll
    for (int nt = 0; nt < NT; nt++) {
        const int col = bcol + wn + 8 * nt + 2 * (lane & 3);
        if (col >= N) continue;
        float sc0 = 1.f, sh0 = 0.f, sc1 = 1.f, sh1 = 0.f;
        if (bias) { sh0 = bias[col]; sh1 = bias[col + 1]; }
        if (bng) {
            float s0 = bng[col]     * rsqrtf(bnv[col]     + 1e-5f);
            float s1 = bng[col + 1] * rsqrtf(bnv[col + 1] + 1e-5f);
            sh0 = (sh0 - bnm[col])     * s0 + bnb[col];
            sh1 = (sh1 - bnm[col + 1]) * s1 + bnb[col + 1];
            sc0 = s0; sc1 = s1;
        }
#pragma unroll
        for (int mt = 0; mt < 2; mt++) {
#pragma unroll
            for (int half = 0; half < 2; half++) {
                const int row = brow + wm + 16 * mt + (lane >> 2) + 8 * half;
                if (row >= M) continue;
                const float* c = acc[mt][nt] + 2 * half;
                float v0 = c[0] * sc0 + sh0;
                float v1 = c[1] * sc1 + sh1;
                if (do_relu) { v0 = fmaxf(v0, 0.f); v1 = fmaxf(v1, 0.f); }
                if (Ch) {
                    bf162 hi = __float22bfloat162_rn(make_float2(v0, v1));
                    float2 hf2 = __bfloat1622float2(hi);
                    bf162 lo = __float22bfloat162_rn(
                        make_float2(v0 - hf2.x, v1 - hf2.y));
                    *(bf162*)(Ch + (size_t)row * N + col) = hi;
                    *(bf162*)(Cl + (size_t)row * N + col) = lo;
                } else {
                    *(float2*)(Cf + (size_t)row * N + col) = make_float2(v0, v1);
                }
            }
        }
    }
}

// ---------------- split fp32 -> bf16 hi/lo planes ----------------
__global__ void split_planes(const float* __restrict__ x,
                             bf16* __restrict__ xh, bf16* __restrict__ xl, int n4)
{
    int i = blockIdx.x * blockDim.x + threadIdx.x;
    if (i >= n4) return;
    float4 v = ((const float4*)x)[i];
    bf162 h0 = __float22bfloat162_rn(make_float2(v.x, v.y));
    bf162 h1 = __float22bfloat162_rn(make_float2(v.z, v.w));
    float2 f0 = __bfloat1622float2(h0);
    float2 f1 = __bfloat1622float2(h1);
    bf162 l0 = __float22bfloat162_rn(make_float2(v.x - f0.x, v.y - f0.y));
    bf162 l1 = __float22bfloat162_rn(make_float2(v.z - f1.x, v.w - f1.y));
    ((bf162*)xh)[i * 2]     = h0;
    ((bf162*)xh)[i * 2 + 1] = h1;
    ((bf162*)xl)[i * 2]     = l0;
    ((bf162*)xl)[i * 2 + 1] = l1;
}

// ---------------- CSR construction ----------------
__global__ void count_deg(const int* __restrict__ dst, int* __restrict__ counts, int E)
{
    int e = blockIdx.x * blockDim.x + threadIdx.x;
    if (e < E) atomicAdd(&counts[dst[e]], 1);
}

__global__ __launch_bounds__(1024) void scan_counts(
    const int* __restrict__ counts, int* __restrict__ rowptr,
    int* __restrict__ fill, int n)
{
    __shared__ int part[1024];
    const int tid = threadIdx.x;
    const int chunk = (n + 1023) / 1024;
    const int begin = min(tid * chunk, n);
    const int end   = min(begin + chunk, n);
    int s = 0;
    for (int i = begin; i < end; i++) s += counts[i];
    part[tid] = s;
    __syncthreads();
    for (int off = 1; off < 1024; off <<= 1) {
        int v = (tid >= off) ? part[tid - off] : 0;
        __syncthreads();
        part[tid] += v;
        __syncthreads();
    }
    int pre = (tid == 0) ? 0 : part[tid - 1];
    for (int i = begin; i < end; i++) {
        rowptr[i] = pre;
        fill[i]   = pre;
        pre += counts[i];
    }
    if (end == n && begin <= n) rowptr[n] = pre;
}

__global__ void fill_csr(const int* __restrict__ src, const int* __restrict__ dst,
                         int* __restrict__ fill, int* __restrict__ csr, int E)
{
    int e = blockIdx.x * blockDim.x + threadIdx.x;
    if (e < E) {
        int pos = atomicAdd(&fill[dst[e]], 1);
        csr[pos] = src[e];
    }
}

// ---------------- CSR gather mean: warp per dst node, writes planes ----------
__global__ void gather_mean(const bf16* __restrict__ hh, const bf16* __restrict__ hl,
                            const int* __restrict__ csr, const int* __restrict__ rowptr,
                            bf16* __restrict__ oh, bf16* __restrict__ ol,
                            int Nn, int D)
{
    const int warp = (blockIdx.x * blockDim.x + threadIdx.x) >> 5;
    const int lane = threadIdx.x & 31;
    if (warp >= Nn) return;
    const int e0 = rowptr[warp];
    const int e1 = rowptr[warp + 1];
    const float inv = 1.f / (float)max(e1 - e0, 1);
    const int nseg = D >> 7;
    float acc[8];
#pragma unroll
    for (int i = 0; i < 8; i++) acc[i] = 0.f;

    for (int e = e0; e < e1; e++) {
        const int s = csr[e];
        const bf16* rh = hh + (size_t)s * D + lane * 4;
        const bf16* rl = hl + (size_t)s * D + lane * 4;
#pragma unroll
        for (int g = 0; g < 2; g++) {
            if (g < nseg) {
                uint2 vh = *(const uint2*)(rh + g * 128);
                uint2 vl = *(const uint2*)(rl + g * 128);
                float2 a0 = __bfloat1622float2(*(const bf162*)&vh.x);
                float2 a1 = __bfloat1622float2(*(const bf162*)&vh.y);
                float2 b0 = __bfloat1622float2(*(const bf162*)&vl.x);
                float2 b1 = __bfloat1622float2(*(const bf162*)&vl.y);
                acc[g * 4 + 0] += a0.x + b0.x;
                acc[g * 4 + 1] += a0.y + b0.y;
                acc[g * 4 + 2] += a1.x + b1.x;
                acc[g * 4 + 3] += a1.y + b1.y;
            }
        }
    }

#pragma unroll
    for (int g = 0; g < 2; g++) {
        if (g < nseg) {
            float v0 = acc[g * 4 + 0] * inv;
            float v1 = acc[g * 4 + 1] * inv;
            float v2 = acc[g * 4 + 2] * inv;
            float v3 = acc[g * 4 + 3] * inv;
            bf162 h0 = __float22bfloat162_rn(make_float2(v0, v1));
            bf162 h1 = __float22bfloat162_rn(make_float2(v2, v3));
            float2 f0 = __bfloat1622float2(h0);
            float2 f1 = __bfloat1622float2(h1);
            bf162 l0 = __float22bfloat162_rn(make_float2(v0 - f0.x, v1 - f0.y));
            bf162 l1 = __float22bfloat162_rn(make_float2(v2 - f1.x, v3 - f1.y));
            uint2 wh_, wl_;
            wh_.x = *(uint32_t*)&h0; wh_.y = *(uint32_t*)&h1;
            wl_.x = *(uint32_t*)&l0; wl_.y = *(uint32_t*)&l1;
            *(uint2*)(oh + (size_t)warp * D + g * 128 + lane * 4) = wh_;
            *(uint2*)(ol + (size_t)warp * D + g * 128 + lane * 4) = wl_;
        }
    }
}

// ---------------- launch helper ----------------
static inline void launch_gemm(
    const bf16* A0h, const bf16* A0l, int K0,
    const bf16* A1h, const bf16* A1l, int K1,
    const bf16* W0h, const bf16* W0l, const bf16* W1h, const bf16* W1l,
    int M, int N,
    const float* bias, const float* bng, const float* bnb,
    const float* bnm, const float* bnv,
    int do_relu, float* Cf, bf16* Ch, bf16* Cl)
{
    if (N >= 128) {
        constexpr int BN_ = 128;
        constexpr int SMEM = 2 * (2 * A_PLANE + 2 * BK * (BN_ + 8)) * 2;
        dim3 grid(N / BN_, (M + BM - 1) / BM);
        gemm_bf16x3<BN_><<<grid, 256, SMEM>>>(
            A0h, A0l, K0, A1h, A1l, K1, W0h, W0l, W1h, W1l, M, N,
            bias, bng, bnb, bnm, bnv, do_relu, Cf, Ch, Cl);
    } else {
        constexpr int BN_ = 64;
        constexpr int SMEM = 2 * (2 * A_PLANE + 2 * BK * (BN_ + 8)) * 2;
        dim3 grid((N + BN_ - 1) / BN_, (M + BM - 1) / BM);
        gemm_bf16x3<BN_><<<grid, 256, SMEM>>>(
            A0h, A0l, K0, A1h, A1l, K1, W0h, W0l, W1h, W1l, M, N,
            bias, bng, bnb, bnm, bnv, do_relu, Cf, Ch, Cl);
    }
}

extern "C" void kernel_launch(void* const* d_in, const int* in_sizes, int n_in,
                              void* d_out, int out_size)
{
    const float* structural = (const float*)d_in[0];
    const float* multimodal = (const float*)d_in[1];
    const int*   src        = (const int*)  d_in[2];
    const int*   dst        = (const int*)  d_in[3];
    const float* enc_w      = (const float*)d_in[4];
    const float* enc_b      = (const float*)d_in[5];
    const float* sage0_ws   = (const float*)d_in[6];
    const float* sage0_wn   = (const float*)d_in[7];
    const float* sage0_b    = (const float*)d_in[8];
    const float* bn0_g      = (const float*)d_in[9];
    const float* bn0_b      = (const float*)d_in[10];
    const float* bn0_m      = (const float*)d_in[11];
    const float* bn0_v      = (const float*)d_in[12];
    const float* sage1_ws   = (const float*)d_in[13];
    const float* sage1_wn   = (const float*)d_in[14];
    const float* sage1_b    = (const float*)d_in[15];
    const float* bn1_g      = (const float*)d_in[16];
    const float* bn1_b      = (const float*)d_in[17];
    const float* bn1_m      = (const float*)d_in[18];
    const float* bn1_v      = (const float*)d_in[19];
    const float* rel_w      = (const float*)d_in[20];
    const float* rel_b      = (const float*)d_in[21];
    const float* cls_w1     = (const float*)d_in[22];
    const float* cls_b1     = (const float*)d_in[23];
    const float* cls_w2     = (const float*)d_in[24];
    const float* cls_b2     = (const float*)d_in[25];
    float* out = (float*)d_out;

#define SYMADDR(var, sym) void* p_##var; cudaGetSymbolAddress(&p_##var, sym);
    SYMADDR(xsh, g_xsh) SYMADDR(xsl, g_xsl) SYMADDR(xmh, g_xmh) SYMADDR(xml, g_xml)
    SYMADDR(h0h, g_h0h) SYMADDR(h0l, g_h0l) SYMADDR(a0h, g_a0h) SYMADDR(a0l, g_a0l)
    SYMADDR(h1h, g_h1h) SYMADDR(h1l, g_h1l) SYMADDR(a1h, g_a1h) SYMADDR(a1l, g_a1l)
    SYMADDR(h2h, g_h2h) SYMADDR(h2l, g_h2l) SYMADDR(hfh, g_hfh) SYMADDR(hfl, g_hfl)
    SYMADDR(c1h, g_c1h) SYMADDR(c1l, g_c1l)
    SYMADDR(wh, g_wh) SYMADDR(wl, g_wl)
    SYMADDR(counts, g_counts) SYMADDR(rowptr, g_rowptr)
    SYMADDR(fill, g_fill) SYMADDR(csr, g_csr)
#undef SYMADDR

    bf16* xsh = (bf16*)p_xsh; bf16* xsl = (bf16*)p_xsl;
    bf16* xmh = (bf16*)p_xmh; bf16* xml = (bf16*)p_xml;
    bf16* h0h = (bf16*)p_h0h; bf16* h0l = (bf16*)p_h0l;
    bf16* a0h = (bf16*)p_a0h; bf16* a0l = (bf16*)p_a0l;
    bf16* h1h = (bf16*)p_h1h; bf16* h1l = (bf16*)p_h1l;
    bf16* a1h = (bf16*)p_a1h; bf16* a1l = (bf16*)p_a1l;
    bf16* h2h = (bf16*)p_h2h; bf16* h2l = (bf16*)p_h2l;
    bf16* hfh = (bf16*)p_hfh; bf16* hfl = (bf16*)p_hfl;
    bf16* c1h = (bf16*)p_c1h; bf16* c1l = (bf16*)p_c1l;
    bf16* wh = (bf16*)p_wh; bf16* wl = (bf16*)p_wl;
    int* counts = (int*)p_counts; int* rowptr = (int*)p_rowptr;
    int* fill   = (int*)p_fill;   int* csr    = (int*)p_csr;

    {
        constexpr int SMEM128 = 2 * (2 * A_PLANE + 2 * BK * (128 + 8)) * 2;
        constexpr int SMEM64  = 2 * (2 * A_PLANE + 2 * BK * (64 + 8)) * 2;
        cudaFuncSetAttribute(gemm_bf16x3<128>,
                             cudaFuncAttributeMaxDynamicSharedMemorySize, SMEM128);
        cudaFuncSetAttribute(gemm_bf16x3<64>,
                             cudaFuncAttributeMaxDynamicSharedMemorySize, SMEM64);
    }

    const int M = N_NODES, E = N_EDGES;

    // ---- CSR build ----
    cudaMemsetAsync(counts, 0, N_NODES * sizeof(int), 0);
    count_deg<<<(E + 255) / 256, 256>>>(dst, counts, E);
    scan_counts<<<1, 1024>>>(counts, rowptr, fill, M);
    fill_csr<<<(E + 255) / 256, 256>>>(src, dst, fill, csr, E);

    // ---- split graph inputs & weights into bf16 hi/lo planes ----
    {
        int n4;
        n4 = (M * 128) / 4;
        split_planes<<<(n4 + 255) / 256, 256>>>(structural, xsh, xsl, n4);
        n4 = (M * 384) / 4;
        split_planes<<<(n4 + 255) / 256, 256>>>(multimodal, xmh, xml, n4);
        n4 = (512 * 128) / 4;
        split_planes<<<(n4 + 255) / 256, 256>>>(enc_w, wh + WOFF_ENC, wl + WOFF_ENC, n4);
        n4 = (128 * 256) / 4;
        split_planes<<<(n4 + 255) / 256, 256>>>(sage0_ws, wh + WOFF_S0S, wl + WOFF_S0S, n4);
        split_planes<<<(n4 + 255) / 256, 256>>>(sage0_wn, wh + WOFF_S0N, wl + WOFF_S0N, n4);
        n4 = (256 * 128) / 4;
        split_planes<<<(n4 + 255) / 256, 256>>>(sage1_ws, wh + WOFF_S1S, wl + WOFF_S1S, n4);
        split_planes<<<(n4 + 255) / 256, 256>>>(sage1_wn, wh + WOFF_S1N, wl + WOFF_S1N, n4);
        split_planes<<<(n4 + 255) / 256, 256>>>(rel_w, wh + WOFF_REL, wl + WOFF_REL, n4);
        n4 = (128 * 64) / 4;
        split_planes<<<(n4 + 255) / 256, 256>>>(cls_w1, wh + WOFF_C1, wl + WOFF_C1, n4);
        n4 = (64 * 32) / 4;
        split_planes<<<(n4 + 255) / 256, 256>>>(cls_w2, wh + WOFF_C2, wl + WOFF_C2, n4);
    }

    // h0 = relu([xs|xm] @ enc_w + enc_b)
    launch_gemm(xsh, xsl, 128, xmh, xml, 384,
                wh + WOFF_ENC, wl + WOFF_ENC,
                wh + WOFF_ENC + 128 * 128, wl + WOFF_ENC + 128 * 128,
                M, 128, enc_b, nullptr, nullptr, nullptr, nullptr, 1,
                nullptr, h0h, h0l);

    // agg0 = mean h0
    gather_mean<<<(M * 32 + 255) / 256, 256>>>(h0h, h0l, csr, rowptr,
                                               a0h, a0l, M, 128);

    // h1 = relu(bn0(h0 @ ws0 + agg0 @ wn0 + b0))
    launch_gemm(h0h, h0l, 128, a0h, a0l, 128,
                wh + WOFF_S0S, wl + WOFF_S0S, wh + WOFF_S0N, wl + WOFF_S0N,
                M, 256, sage0_b, bn0_g, bn0_b, bn0_m, bn0_v, 1,
                nullptr, h1h, h1l);

    // agg1 = mean h1
    gather_mean<<<(M * 32 + 255) / 256, 256>>>(h1h, h1l, csr, rowptr,
                                               a1h, a1l, M, 256);

    // h2 = relu(bn1(h1 @ ws1 + agg1 @ wn1 + b1))
    launch_gemm(h1h, h1l, 256, a1h, a1l, 256,
                wh + WOFF_S1S, wl + WOFF_S1S, wh + WOFF_S1N, wl + WOFF_S1N,
                M, 128, sage1_b, bn1_g, bn1_b, bn1_m, bn1_v, 1,
                nullptr, h2h, h2l);

    // hf = relu([h0|h2] @ rel_w + rel_b)
    launch_gemm(h0h, h0l, 128, h2h, h2l, 128,
                wh + WOFF_REL, wl + WOFF_REL,
                wh + WOFF_REL + 128 * 128, wl + WOFF_REL + 128 * 128,
                M, 128, rel_b, nullptr, nullptr, nullptr, nullptr, 1,
                nullptr, hfh, hfl);

    // c1 = relu(hf @ cls_w1 + cls_b1)
    launch_gemm(hfh, hfl, 128, hfh, hfl, 0,
                wh + WOFF_C1, wl + WOFF_C1, wh + WOFF_C1, wl + WOFF_C1,
                M, 64, cls_b1, nullptr, nullptr, nullptr, nullptr, 1,
                nullptr, c1h, c1l);

    // out = c1 @ cls_w2 + cls_b2   (fp32)
    launch_gemm(c1h, c1l, 64, c1h, c1l, 0,
                wh + WOFF_C2, wl + WOFF_C2, wh + WOFF_C2, wl + WOFF_C2,
                M, 32, cls_b2, nullptr, nullptr, nullptr, nullptr, 0,
                out, nullptr, nullptr);
}